// round 13
// baseline (speedup 1.0000x reference)
#include <cuda_runtime.h>
#include <cuda_bf16.h>
#include <cstdint>

#define NB    32
#define LP    2048
#define LDRG  256
#define DD    512
#define GPNUM 512

typedef unsigned short u16;

// ======================= scratch (floats) =======================
__device__ float g_scratch[85458944];
__device__ unsigned char g_masks[24576];
__device__ int g_flag;

__device__ __forceinline__ u16 bf16bits(float x) {
  __nv_bfloat16 h = __float2bfloat16_rn(x);
  return *reinterpret_cast<u16*>(&h);
}
__device__ __forceinline__ float bf16val(u16 b) {
  __nv_bfloat16 h = *reinterpret_cast<__nv_bfloat16*>(&b);
  return __bfloat162float(h);
}
__device__ __forceinline__ void split2(float v0, float v1, uint32_t& hi, uint32_t& lo) {
  u16 h0 = bf16bits(v0), h1 = bf16bits(v1);
  u16 l0 = bf16bits(v0 - bf16val(h0)), l1 = bf16bits(v1 - bf16val(h1));
  hi = (uint32_t)h0 | ((uint32_t)h1 << 16);
  lo = (uint32_t)l0 | ((uint32_t)l1 << 16);
}
__device__ __forceinline__ uint32_t smaddr(const void* p) {
  return (uint32_t)__cvta_generic_to_shared(p);
}

// cp.async helpers
#define CP16(s, g) \
  asm volatile("cp.async.cg.shared.global [%0], [%1], 16;" :: "r"(s), "l"(g))
#define CP_COMMIT() asm volatile("cp.async.commit_group;" ::: "memory")
#define CP_WAIT0() asm volatile("cp.async.wait_group 0;" ::: "memory")
#define CP_WAIT1() asm volatile("cp.async.wait_group 1;" ::: "memory")

// ======================= masks =======================
__device__ __forceinline__ bool read_mask(const void* p, int i, int f) {
  if (f == 0) return ((const unsigned char*)p)[i] != 0;
  if (f == 1) return ((const int*)p)[i] != 0;
  return ((const float*)p)[i] != 0.0f;
}
__global__ void detect_kernel(const unsigned char* __restrict__ p) {
  int big = 0, off = 0;
  for (int i = 0; i < 1024; ++i) {
    unsigned char c = p[i];
    big |= (c > 1) ? 1 : 0;
    off |= (c != 0 && (i & 3) != 0) ? 1 : 0;
  }
  g_flag = big ? 2 : (off ? 0 : 1);
}
__global__ void mask_kernel(const void* __restrict__ mp, const void* __restrict__ md,
                            float* __restrict__ outMP, float* __restrict__ outMD) {
  int f = g_flag;
  int idx = blockIdx.x * blockDim.x + threadIdx.x;
  if (idx < NB * GPNUM) {
    int b = idx / GPNUM, g = idx % GPNUM;
    int base = b * LP + g * 4;
    bool any = false;
#pragma unroll
    for (int r = 0; r < 4; ++r) any = any || read_mask(mp, base + r, f);
    g_masks[idx] = any ? 1 : 0;
    outMP[idx] = any ? 1.0f : 0.0f;
  } else {
    int j = idx - NB * GPNUM;
    if (j < NB * LDRG) {
      bool v = read_mask(md, j, f);
      g_masks[16384 + j] = v ? 1 : 0;
      outMD[j] = v ? 1.0f : 0.0f;
    }
  }
}

// ============== grouping + conversions (ILP x4) ==============
__global__ void group_bf16_v4(const float* __restrict__ P,
                              uint2* __restrict__ H, uint2* __restrict__ L) {
#pragma unroll
  for (int it = 0; it < 4; ++it) {
    int idx = blockIdx.x * 1024 + it * 256 + threadIdx.x;
    int d4 = idx & 127;
    int g = (idx >> 7) & 511;
    int b = idx >> 16;
    const float* p = P + ((size_t)b * LP + (size_t)g * 4) * DD + d4 * 4;
    float4 x0 = *(const float4*)p;
    float4 x1 = *(const float4*)(p + 512);
    float4 x2 = *(const float4*)(p + 1024);
    float4 x3 = *(const float4*)(p + 1536);
    float v0 = 0.25f * (x0.x + x1.x + x2.x + x3.x);
    float v1 = 0.25f * (x0.y + x1.y + x2.y + x3.y);
    float v2 = 0.25f * (x0.z + x1.z + x2.z + x3.z);
    float v3 = 0.25f * (x0.w + x1.w + x2.w + x3.w);
    uint32_t h01, l01, h23, l23;
    split2(v0, v1, h01, l01);
    split2(v2, v3, h23, l23);
    H[idx] = make_uint2(h01, h23);
    L[idx] = make_uint2(l01, l23);
  }
}

__global__ void cvt_bf16_v4(const float4* __restrict__ X, int n4,
                            uint2* __restrict__ H, uint2* __restrict__ L) {
#pragma unroll
  for (int it = 0; it < 4; ++it) {
    int i = blockIdx.x * 1024 + it * 256 + threadIdx.x;
    if (i >= n4) continue;
    float4 x = X[i];
    uint32_t h01, l01, h23, l23;
    split2(x.x, x.y, h01, l01);
    split2(x.z, x.w, h23, l23);
    H[i] = make_uint2(h01, h23);
    L[i] = make_uint2(l01, l23);
  }
}

__global__ void cvt_w6(const float4* w0, const float4* w1, const float4* w2,
                       const float4* w3, const float4* w4, const float4* w5,
                       uint2* __restrict__ H, uint2* __restrict__ L) {
  int wi = blockIdx.y;
  const float4* X = (wi == 0) ? w0 : (wi == 1) ? w1 : (wi == 2) ? w2
                   : (wi == 3) ? w3 : (wi == 4) ? w4 : w5;
#pragma unroll
  for (int it = 0; it < 4; ++it) {
    int i = blockIdx.x * 1024 + it * 256 + threadIdx.x;
    float4 x = X[i];
    uint32_t h01, l01, h23, l23;
    split2(x.x, x.y, h01, l01);
    split2(x.z, x.w, h23, l23);
    size_t o = (size_t)wi * 65536 + i;
    H[o] = make_uint2(h01, h23);
    L[o] = make_uint2(l01, l23);
  }
}

// ======================= MMA / ldmatrix macros =======================
#define MMA_BF16(c, a, b)                                                      \
  asm volatile("mma.sync.aligned.m16n8k16.row.col.f32.bf16.bf16.f32 "          \
               "{%0,%1,%2,%3}, {%4,%5,%6,%7}, {%8,%9}, {%0,%1,%2,%3};"         \
               : "+f"((c)[0]), "+f"((c)[1]), "+f"((c)[2]), "+f"((c)[3])        \
               : "r"((a)[0]), "r"((a)[1]), "r"((a)[2]), "r"((a)[3]),           \
                 "r"((b)[0]), "r"((b)[1]))

#define LDSM_X4(r0, r1, r2, r3, a)                                             \
  asm volatile("ldmatrix.sync.aligned.m8n8.x4.shared.b16 {%0,%1,%2,%3}, [%4];" \
               : "=r"(r0), "=r"(r1), "=r"(r2), "=r"(r3) : "r"(a))

#define LDSM_X4_T(r0, r1, r2, r3, a)                                           \
  asm volatile("ldmatrix.sync.aligned.m8n8.x4.trans.shared.b16 {%0,%1,%2,%3}, [%4];" \
               : "=r"(r0), "=r"(r1), "=r"(r2), "=r"(r3) : "r"(a))

// ====== bf16x3 projection (cp.async double-buffered) ======
#define PROJ_SMEM 61440
__global__ __launch_bounds__(256) void gemm_proj_mma(
    const u16* __restrict__ Ah, const u16* __restrict__ Al,
    const u16* __restrict__ Wh, const u16* __restrict__ Wl,
    u16* __restrict__ Ch, u16* __restrict__ Cl) {
  extern __shared__ __align__(16) u16 dyn[];
  u16* AhB = dyn;
  u16* AlB = dyn + 10240;
  u16* BhB = dyn + 20480;
  u16* BlB = dyn + 25600;

  const int tid = threadIdx.x;
  const int w = tid >> 5, lane = tid & 31;
  const int g = lane >> 2, t4 = lane & 3;
  const int wm = (w >> 1) * 32, wn = (w & 1) * 32;
  const int mBase = blockIdx.x * 128;
  const int nBase = blockIdx.y * 64;

  const int lane15 = lane & 15;
  const int hi8 = (lane >> 4) << 3;
  const uint32_t aAddrH = smaddr(AhB + (wm + lane15) * 40 + hi8);
  const uint32_t aAddrL = smaddr(AlB + (wm + lane15) * 40 + hi8);
  const int bn = (lane & 7) + hi8;
  const int bk = lane & 8;
  const uint32_t bAddrH = smaddr(BhB + (wn + bn) * 40 + bk);
  const uint32_t bAddrL = smaddr(BlB + (wn + bn) * 40 + bk);

  auto loadTile = [&](int k0, int buf) {
#pragma unroll
    for (int u = tid; u < 512; u += 256) {
      int row = u >> 2, seg = u & 3;
      size_t ga = (size_t)(mBase + row) * 512 + k0 + seg * 8;
      int so = buf * 5120 + row * 40 + seg * 8;
      CP16(smaddr(AhB + so), Ah + ga);
      CP16(smaddr(AlB + so), Al + ga);
    }
    {
      int row = tid >> 2, seg = tid & 3;
      size_t ga = (size_t)(nBase + row) * 512 + k0 + seg * 8;
      int so = buf * 2560 + row * 40 + seg * 8;
      CP16(smaddr(BhB + so), Wh + ga);
      CP16(smaddr(BlB + so), Wl + ga);
    }
    CP_COMMIT();
  };

  float acc[2][4][4];
#pragma unroll
  for (int mi = 0; mi < 2; ++mi)
#pragma unroll
    for (int j = 0; j < 4; ++j)
#pragma unroll
      for (int q = 0; q < 4; ++q) acc[mi][j][q] = 0.0f;

  loadTile(0, 0);
  for (int t = 0; t < 16; ++t) {
    if (t < 15) { loadTile((t + 1) * 32, (t + 1) & 1); CP_WAIT1(); }
    else CP_WAIT0();
    __syncthreads();
    const uint32_t aOff = (uint32_t)((t & 1) * 10240);
    const uint32_t bOff = (uint32_t)((t & 1) * 5120);
#pragma unroll
    for (int kk = 0; kk < 32; kk += 16) {
      uint32_t ah[2][4], al[2][4];
#pragma unroll
      for (int mi = 0; mi < 2; ++mi) {
        LDSM_X4(ah[mi][0], ah[mi][1], ah[mi][2], ah[mi][3], aAddrH + aOff + (mi * 640 + kk) * 2);
        LDSM_X4(al[mi][0], al[mi][1], al[mi][2], al[mi][3], aAddrL + aOff + (mi * 640 + kk) * 2);
      }
      uint32_t bh[4][2], bl[4][2];
#pragma unroll
      for (int p = 0; p < 2; ++p) {
        LDSM_X4(bh[2 * p][0], bh[2 * p][1], bh[2 * p + 1][0], bh[2 * p + 1][1],
                bAddrH + bOff + (p * 640 + kk) * 2);
        LDSM_X4(bl[2 * p][0], bl[2 * p][1], bl[2 * p + 1][0], bl[2 * p + 1][1],
                bAddrL + bOff + (p * 640 + kk) * 2);
      }
#pragma unroll
      for (int mi = 0; mi < 2; ++mi)
#pragma unroll
        for (int j = 0; j < 4; ++j) {
          MMA_BF16(acc[mi][j], ah[mi], bh[j]);
          MMA_BF16(acc[mi][j], ah[mi], bl[j]);
          MMA_BF16(acc[mi][j], al[mi], bh[j]);
        }
    }
    __syncthreads();
  }

#pragma unroll
  for (int mi = 0; mi < 2; ++mi) {
    int row = mBase + wm + mi * 16 + g;
#pragma unroll
    for (int j = 0; j < 4; ++j) {
      int col = nBase + wn + j * 8 + t4 * 2;
      uint32_t hi, lo;
      split2(acc[mi][j][0], acc[mi][j][1], hi, lo);
      *(uint32_t*)(Ch + (size_t)row * 512 + col) = hi;
      *(uint32_t*)(Cl + (size_t)row * 512 + col) = lo;
      split2(acc[mi][j][2], acc[mi][j][3], hi, lo);
      *(uint32_t*)(Ch + (size_t)(row + 8) * 512 + col) = hi;
      *(uint32_t*)(Cl + (size_t)(row + 8) * 512 + col) = lo;
    }
  }
}

// ====== bf16x3 logits (cp.async, T=2): masked, writes bf16 hi|lo into S ======
// S slice per z: Lq rows x 2*Lk u16 => z stride = 2*Lq*Lk u16
#define LOGITS_SMEM 61440
__global__ __launch_bounds__(256) void gemm_logits_mma(
    const u16* __restrict__ Qh, const u16* __restrict__ Ql,
    const u16* __restrict__ Kh, const u16* __restrict__ Kl,
    float* __restrict__ S,
    const unsigned char* __restrict__ mq, const unsigned char* __restrict__ mk,
    int Lq, int Lk) {
  extern __shared__ __align__(16) u16 dyn[];
  u16* AhB = dyn;
  u16* AlB = dyn + 10240;
  u16* BhB = dyn + 20480;
  u16* BlB = dyn + 25600;

  const int tid = threadIdx.x;
  const int w = tid >> 5, lane = tid & 31;
  const int g = lane >> 2, t4 = lane & 3;
  const int wm = (w >> 1) * 32, wn = (w & 1) * 32;
  const int mBase = blockIdx.x * 128;
  const int nBase = blockIdx.y * 64;
  const int z = blockIdx.z;
  const int b = z >> 3, h = z & 7;
  const u16* Ahg = Qh + (size_t)b * Lq * 512 + h * 64;
  const u16* Alg = Ql + (size_t)b * Lq * 512 + h * 64;
  const u16* Bhg = Kh + (size_t)b * Lk * 512 + h * 64;
  const u16* Blg = Kl + (size_t)b * Lk * 512 + h * 64;
  u16* Sbase = (u16*)S + (size_t)z * 2 * Lq * Lk;
  const unsigned char* mqb = mq + b * Lq;
  const unsigned char* mkb = mk + b * Lk;

  const int lane15 = lane & 15;
  const int hi8 = (lane >> 4) << 3;
  const uint32_t aAddrH = smaddr(AhB + (wm + lane15) * 40 + hi8);
  const uint32_t aAddrL = smaddr(AlB + (wm + lane15) * 40 + hi8);
  const int bn = (lane & 7) + hi8;
  const int bk = lane & 8;
  const uint32_t bAddrH = smaddr(BhB + (wn + bn) * 40 + bk);
  const uint32_t bAddrL = smaddr(BlB + (wn + bn) * 40 + bk);

  auto loadTile = [&](int k0, int buf) {
#pragma unroll
    for (int u = tid; u < 512; u += 256) {
      int row = u >> 2, seg = u & 3;
      size_t ga = (size_t)(mBase + row) * 512 + k0 + seg * 8;
      int so = buf * 5120 + row * 40 + seg * 8;
      CP16(smaddr(AhB + so), Ahg + ga);
      CP16(smaddr(AlB + so), Alg + ga);
    }
    {
      int row = tid >> 2, seg = tid & 3;
      size_t ga = (size_t)(nBase + row) * 512 + k0 + seg * 8;
      int so = buf * 2560 + row * 40 + seg * 8;
      CP16(smaddr(BhB + so), Bhg + ga);
      CP16(smaddr(BlB + so), Blg + ga);
    }
    CP_COMMIT();
  };

  float acc[2][4][4];
#pragma unroll
  for (int mi = 0; mi < 2; ++mi)
#pragma unroll
    for (int j = 0; j < 4; ++j)
#pragma unroll
      for (int q = 0; q < 4; ++q) acc[mi][j][q] = 0.0f;

  loadTile(0, 0);
#pragma unroll
  for (int t = 0; t < 2; ++t) {
    if (t < 1) { loadTile(32, 1); CP_WAIT1(); }
    else CP_WAIT0();
    __syncthreads();
    const uint32_t aOff = (uint32_t)(t * 10240);
    const uint32_t bOff = (uint32_t)(t * 5120);
#pragma unroll
    for (int kk = 0; kk < 32; kk += 16) {
      uint32_t ah[2][4], al[2][4];
#pragma unroll
      for (int mi = 0; mi < 2; ++mi) {
        LDSM_X4(ah[mi][0], ah[mi][1], ah[mi][2], ah[mi][3], aAddrH + aOff + (mi * 640 + kk) * 2);
        LDSM_X4(al[mi][0], al[mi][1], al[mi][2], al[mi][3], aAddrL + aOff + (mi * 640 + kk) * 2);
      }
      uint32_t bh[4][2], bl[4][2];
#pragma unroll
      for (int p = 0; p < 2; ++p) {
        LDSM_X4(bh[2 * p][0], bh[2 * p][1], bh[2 * p + 1][0], bh[2 * p + 1][1],
                bAddrH + bOff + (p * 640 + kk) * 2);
        LDSM_X4(bl[2 * p][0], bl[2 * p][1], bl[2 * p + 1][0], bl[2 * p + 1][1],
                bAddrL + bOff + (p * 640 + kk) * 2);
      }
#pragma unroll
      for (int mi = 0; mi < 2; ++mi)
#pragma unroll
        for (int j = 0; j < 4; ++j) {
          MMA_BF16(acc[mi][j], ah[mi], bh[j]);
          MMA_BF16(acc[mi][j], ah[mi], bl[j]);
          MMA_BF16(acc[mi][j], al[mi], bh[j]);
        }
    }
    __syncthreads();
  }

#pragma unroll
  for (int mi = 0; mi < 2; ++mi) {
    int row = mBase + wm + mi * 16 + g;
    float p0 = mqb[row] ? 0.0f : 1.0e6f;
    float p1 = mqb[row + 8] ? 0.0f : 1.0e6f;
    u16* r0p = Sbase + (size_t)row * 2 * Lk;
    u16* r1p = Sbase + (size_t)(row + 8) * 2 * Lk;
#pragma unroll
    for (int j = 0; j < 4; ++j) {
      int col = wn + nBase + j * 8 + t4 * 2;
      float c0 = mkb[col] ? 0.0f : 1.0e6f;
      float c1 = mkb[col + 1] ? 0.0f : 1.0e6f;
      uint32_t hi, lo;
      split2(acc[mi][j][0] - fmaxf(p0, c0), acc[mi][j][1] - fmaxf(p0, c1), hi, lo);
      *(uint32_t*)(r0p + col) = hi;
      *(uint32_t*)(r0p + Lk + col) = lo;
      split2(acc[mi][j][2] - fmaxf(p1, c0), acc[mi][j][3] - fmaxf(p1, c1), hi, lo);
      *(uint32_t*)(r1p + col) = hi;
      *(uint32_t*)(r1p + Lk + col) = lo;
    }
  }
}

// ---------------- softmax: bf16 hi|lo in S -> alpha fp32 out + bf16 hi/lo in-place ----------------
template <int LK>
__global__ __launch_bounds__(256) void softmax_kernel(
    float* __restrict__ S, const unsigned char* __restrict__ mq,
    float* __restrict__ alphaOut, int Lq) {
  __shared__ float sbuf[8][LK + 1];
  const int l = blockIdx.x, b = blockIdx.y;
  const int tid = threadIdx.x, w = tid >> 5, lane = tid & 31;
  const size_t abase = ((size_t)b * Lq + l) * (size_t)(LK * 8);
  u16* srow = (u16*)S + ((size_t)(b * 8 + w) * Lq + l) * 2 * LK;

  if (!mq[b * Lq + l]) {
    for (int idx = tid; idx < LK * 8; idx += 256) alphaOut[abase + idx] = 0.0f;
    for (int k = lane; k < LK; k += 32) ((uint32_t*)srow)[k] = 0;  // zero hi+lo halves
    return;
  }

  const int nit4 = LK / 128;
  float v[LK / 32];
  float mx = -3.0e38f;
#pragma unroll
  for (int i = 0; i < nit4; ++i) {
    uint2 Hv = *(const uint2*)(srow + lane * 4 + 128 * i);
    uint2 Lv = *(const uint2*)(srow + LK + lane * 4 + 128 * i);
    float a0 = bf16val((u16)(Hv.x & 0xffffu)) + bf16val((u16)(Lv.x & 0xffffu));
    float a1 = bf16val((u16)(Hv.x >> 16)) + bf16val((u16)(Lv.x >> 16));
    float a2 = bf16val((u16)(Hv.y & 0xffffu)) + bf16val((u16)(Lv.y & 0xffffu));
    float a3 = bf16val((u16)(Hv.y >> 16)) + bf16val((u16)(Lv.y >> 16));
    v[4 * i] = a0; v[4 * i + 1] = a1; v[4 * i + 2] = a2; v[4 * i + 3] = a3;
    mx = fmaxf(mx, fmaxf(fmaxf(a0, a1), fmaxf(a2, a3)));
  }
#pragma unroll
  for (int o = 16; o > 0; o >>= 1) mx = fmaxf(mx, __shfl_xor_sync(0xffffffffu, mx, o));
  float sum = 0.0f;
#pragma unroll
  for (int q = 0; q < LK / 32; ++q) { float e = __expf(v[q] - mx); v[q] = e; sum += e; }
#pragma unroll
  for (int o = 16; o > 0; o >>= 1) sum += __shfl_xor_sync(0xffffffffu, sum, o);
  float inv = 1.0f / sum;
#pragma unroll
  for (int i = 0; i < nit4; ++i) {
    float a0 = v[4 * i] * inv, a1 = v[4 * i + 1] * inv;
    float a2 = v[4 * i + 2] * inv, a3 = v[4 * i + 3] * inv;
    int k = lane * 4 + 128 * i;
    sbuf[w][k] = a0; sbuf[w][k + 1] = a1; sbuf[w][k + 2] = a2; sbuf[w][k + 3] = a3;
    uint32_t h01, l01, h23, l23;
    split2(a0, a1, h01, l01);
    split2(a2, a3, h23, l23);
    *(uint2*)(srow + k) = make_uint2(h01, h23);
    *(uint2*)(srow + LK + k) = make_uint2(l01, l23);
  }
  __syncthreads();
#pragma unroll 4
  for (int idx = tid; idx < LK * 8; idx += 256) {
    int k = idx >> 3, h = idx & 7;
    alphaOut[abase + idx] = sbuf[h][k];
  }
}

// ====== bf16x3 AV (cp.async double-buffered) ======
#define AV_SMEM 59392
__global__ __launch_bounds__(256) void gemm_av_mma(
    const float* __restrict__ S, const u16* __restrict__ Vh, const u16* __restrict__ Vl,
    float* __restrict__ Out, int Lq, int Lk) {
  extern __shared__ __align__(16) u16 dyn[];
  u16* AhB = dyn;
  u16* AlB = dyn + 10240;
  u16* BhB = dyn + 20480;
  u16* BlB = dyn + 25088;

  const int tid = threadIdx.x;
  const int w = tid >> 5, lane = tid & 31;
  const int g = lane >> 2, t4 = lane & 3;
  const int wm = (w >> 1) * 32, wn = (w & 1) * 32;
  const int mBase = blockIdx.x * 128;
  const int z = blockIdx.z;
  const int b = z >> 3, h = z & 7;
  const u16* Abase = (const u16*)S + (size_t)z * 2 * Lq * Lk;
  const size_t vbase = (size_t)b * Lk * 512 + h * 64;
  float* C = Out + (size_t)b * Lq * 512 + h * 64;

  const int lane15 = lane & 15;
  const int hi8 = (lane >> 4) << 3;
  const uint32_t aAddrH = smaddr(AhB + (wm + lane15) * 40 + hi8);
  const uint32_t aAddrL = smaddr(AlB + (wm + lane15) * 40 + hi8);
  const int bkOff = (lane & 7) + (lane & 8);
  const uint32_t bAddrH = smaddr(BhB + bkOff * 72 + wn + hi8);
  const uint32_t bAddrL = smaddr(BlB + bkOff * 72 + wn + hi8);

  auto loadTile = [&](int k0, int buf) {
#pragma unroll
    for (int u = tid; u < 512; u += 256) {
      int row = u >> 2, seg = u & 3;
      const u16* ar = Abase + (size_t)(mBase + row) * 2 * Lk + k0 + seg * 8;
      int so = buf * 5120 + row * 40 + seg * 8;
      CP16(smaddr(AhB + so), ar);
      CP16(smaddr(AlB + so), ar + Lk);
    }
    {
      int row = tid >> 3, seg = tid & 7;
      size_t ga = vbase + (size_t)(k0 + row) * 512 + seg * 8;
      int so = buf * 2304 + row * 72 + seg * 8;
      CP16(smaddr(BhB + so), Vh + ga);
      CP16(smaddr(BlB + so), Vl + ga);
    }
    CP_COMMIT();
  };

  float acc[2][4][4];
#pragma unroll
  for (int mi = 0; mi < 2; ++mi)
#pragma unroll
    for (int j = 0; j < 4; ++j)
#pragma unroll
      for (int q = 0; q < 4; ++q) acc[mi][j][q] = 0.0f;

  const int T = Lk / 32;
  loadTile(0, 0);
  for (int t = 0; t < T; ++t) {
    if (t < T - 1) { loadTile((t + 1) * 32, (t + 1) & 1); CP_WAIT1(); }
    else CP_WAIT0();
    __syncthreads();
    const uint32_t aOff = (uint32_t)((t & 1) * 10240);
    const uint32_t bOff = (uint32_t)((t & 1) * 4608);
#pragma unroll
    for (int kk = 0; kk < 32; kk += 16) {
      uint32_t ah[2][4], al[2][4];
#pragma unroll
      for (int mi = 0; mi < 2; ++mi) {
        LDSM_X4(ah[mi][0], ah[mi][1], ah[mi][2], ah[mi][3], aAddrH + aOff + (mi * 640 + kk) * 2);
        LDSM_X4(al[mi][0], al[mi][1], al[mi][2], al[mi][3], aAddrL + aOff + (mi * 640 + kk) * 2);
      }
      uint32_t bh[4][2], bl[4][2];
#pragma unroll
      for (int p = 0; p < 2; ++p) {
        LDSM_X4_T(bh[2 * p][0], bh[2 * p][1], bh[2 * p + 1][0], bh[2 * p + 1][1],
                  bAddrH + bOff + (kk * 72 + p * 16) * 2);
        LDSM_X4_T(bl[2 * p][0], bl[2 * p][1], bl[2 * p + 1][0], bl[2 * p + 1][1],
                  bAddrL + bOff + (kk * 72 + p * 16) * 2);
      }
#pragma unroll
      for (int mi = 0; mi < 2; ++mi)
#pragma unroll
        for (int j = 0; j < 4; ++j) {
          MMA_BF16(acc[mi][j], ah[mi], bh[j]);
          MMA_BF16(acc[mi][j], ah[mi], bl[j]);
          MMA_BF16(acc[mi][j], al[mi], bh[j]);
        }
    }
    __syncthreads();
  }

#pragma unroll
  for (int mi = 0; mi < 2; ++mi) {
    int row = mBase + wm + mi * 16 + g;
#pragma unroll
    for (int j = 0; j < 4; ++j) {
      int col = wn + j * 8 + t4 * 2;
      *(float2*)(C + (size_t)row * 512 + col) = make_float2(acc[mi][j][0], acc[mi][j][1]);
      *(float2*)(C + (size_t)(row + 8) * 512 + col) = make_float2(acc[mi][j][2], acc[mi][j][3]);
    }
  }
}

// ---------------- launch ----------------
extern "C" void kernel_launch(void* const* d_in, const int* in_sizes, int n_in,
                              void* d_out, int out_size) {
  const float* protein = (const float*)d_in[0];
  const float* drug    = (const float*)d_in[1];
  const void*  mpraw   = d_in[2];
  const void*  mdraw   = d_in[3];
  const float* W[6] = {(const float*)d_in[4], (const float*)d_in[5], (const float*)d_in[6],
                       (const float*)d_in[7], (const float*)d_in[8], (const float*)d_in[9]};
  float* out = (float*)d_out;

  float* sc = nullptr;
  cudaGetSymbolAddress((void**)&sc, g_scratch);
  unsigned char* mg = nullptr;
  cudaGetSymbolAddress((void**)&mg, g_masks);

  float* Sb = sc;
  u16* QPh = (u16*)(sc + 33554432); u16* QPl = (u16*)(sc + 37748736);
  u16* KPh = (u16*)(sc + 41943040); u16* KPl = (u16*)(sc + 46137344);
  u16* VPh = (u16*)(sc + 50331648); u16* VPl = (u16*)(sc + 54525952);
  u16* QDh = (u16*)(sc + 58720256); u16* QDl = (u16*)(sc + 60817408);
  u16* KDh = (u16*)(sc + 62914560); u16* KDl = (u16*)(sc + 65011712);
  u16* VDh = (u16*)(sc + 67108864); u16* VDl = (u16*)(sc + 69206016);
  u16* PGH = (u16*)(sc + 71303168); u16* PGL = (u16*)(sc + 75497472);
  u16* DRH = (u16*)(sc + 79691776); u16* DRL = (u16*)(sc + 81788928);
  u16* WHb = (u16*)(sc + 83886080); u16* WLb = (u16*)(sc + 84672512);
  unsigned char* mpg = mg;
  unsigned char* mdg = mg + 16384;

  const size_t OFF_PROT = 0;
  const size_t OFF_DRUG = 8388608;
  const size_t OFF_MP   = 12582912;
  const size_t OFF_MD   = 12599296;
  const size_t OFF_APD  = 12607488;
  const size_t OFF_ADP  = 46161920;

  static int attr_done = 0;
  if (!attr_done) {
    cudaFuncSetAttribute(gemm_proj_mma, cudaFuncAttributeMaxDynamicSharedMemorySize, PROJ_SMEM);
    cudaFuncSetAttribute(gemm_logits_mma, cudaFuncAttributeMaxDynamicSharedMemorySize, LOGITS_SMEM);
    cudaFuncSetAttribute(gemm_av_mma, cudaFuncAttributeMaxDynamicSharedMemorySize, AV_SMEM);
    attr_done = 1;
  }

  detect_kernel<<<1, 1>>>((const unsigned char*)mpraw);
  mask_kernel<<<96, 256>>>(mpraw, mdraw, out + OFF_MP, out + OFF_MD);
  group_bf16_v4<<<2048, 256>>>(protein, (uint2*)PGH, (uint2*)PGL);
  cvt_bf16_v4<<<1024, 256>>>((const float4*)drug, 1048576, (uint2*)DRH, (uint2*)DRL);
  cvt_w6<<<dim3(64, 6), 256>>>((const float4*)W[0], (const float4*)W[1], (const float4*)W[2],
                               (const float4*)W[3], (const float4*)W[4], (const float4*)W[5],
                               (uint2*)WHb, (uint2*)WLb);

  // projections -> bf16 hi/lo
  u16* PH[3] = {QPh, KPh, VPh}; u16* PL[3] = {QPl, KPl, VPl};
  for (int i = 0; i < 3; ++i)
    gemm_proj_mma<<<dim3(128, 8), 256, PROJ_SMEM>>>(PGH, PGL, WHb + (size_t)i * 262144,
                                                    WLb + (size_t)i * 262144, PH[i], PL[i]);
  u16* DH[3] = {QDh, KDh, VDh}; u16* DL[3] = {QDl, KDl, VDl};
  for (int i = 0; i < 3; ++i)
    gemm_proj_mma<<<dim3(64, 8), 256, PROJ_SMEM>>>(DRH, DRL, WHb + (size_t)(i + 3) * 262144,
                                                   WLb + (size_t)(i + 3) * 262144, DH[i], DL[i]);

  // protein->drug: Lq=512, Lk=256
  gemm_logits_mma<<<dim3(4, 4, 256), 256, LOGITS_SMEM>>>(QPh, QPl, KDh, KDl, Sb, mpg, mdg, 512, 256);
  softmax_kernel<256><<<dim3(512, 32), 256>>>(Sb, mpg, out + OFF_APD, 512);
  gemm_av_mma<<<dim3(4, 1, 256), 256, AV_SMEM>>>(Sb, VDh, VDl, out + OFF_PROT, 512, 256);

  // drug->protein: Lq=256, Lk=512
  gemm_logits_mma<<<dim3(2, 8, 256), 256, LOGITS_SMEM>>>(QDh, QDl, KPh, KPl, Sb, mdg, mpg, 256, 512);
  softmax_kernel<512><<<dim3(256, 32), 256>>>(Sb, mdg, out + OFF_ADP, 256);
  gemm_av_mma<<<dim3(2, 1, 256), 256, AV_SMEM>>>(Sb, VPh, VPl, out + OFF_DRUG, 256, 512);

  (void)in_sizes; (void)n_in; (void)out_size;
}

// round 14
// speedup vs baseline: 1.1002x; 1.1002x over previous
#include <cuda_runtime.h>
#include <cuda_bf16.h>
#include <cstdint>

#define NB    32
#define LP    2048
#define LDRG  256
#define DD    512
#define GPNUM 512

typedef unsigned short u16;

// ======================= scratch (floats) =======================
// S1 @0 (33554432), Q/K/V bf16 @33554432.., PG/DR/W @71303168.., S2 @85458944
__device__ float g_scratch[119013376];
__device__ unsigned char g_masks[24576];
__device__ int g_flag;

__device__ __forceinline__ u16 bf16bits(float x) {
  __nv_bfloat16 h = __float2bfloat16_rn(x);
  return *reinterpret_cast<u16*>(&h);
}
__device__ __forceinline__ float bf16val(u16 b) {
  __nv_bfloat16 h = *reinterpret_cast<__nv_bfloat16*>(&b);
  return __bfloat162float(h);
}
__device__ __forceinline__ void split2(float v0, float v1, uint32_t& hi, uint32_t& lo) {
  u16 h0 = bf16bits(v0), h1 = bf16bits(v1);
  u16 l0 = bf16bits(v0 - bf16val(h0)), l1 = bf16bits(v1 - bf16val(h1));
  hi = (uint32_t)h0 | ((uint32_t)h1 << 16);
  lo = (uint32_t)l0 | ((uint32_t)l1 << 16);
}
__device__ __forceinline__ uint32_t smaddr(const void* p) {
  return (uint32_t)__cvta_generic_to_shared(p);
}

#define CP16(s, g) \
  asm volatile("cp.async.cg.shared.global [%0], [%1], 16;" :: "r"(s), "l"(g))
#define CP_COMMIT() asm volatile("cp.async.commit_group;" ::: "memory")
#define CP_WAIT0() asm volatile("cp.async.wait_group 0;" ::: "memory")
#define CP_WAIT1() asm volatile("cp.async.wait_group 1;" ::: "memory")

// ======================= masks =======================
__device__ __forceinline__ bool read_mask(const void* p, int i, int f) {
  if (f == 0) return ((const unsigned char*)p)[i] != 0;
  if (f == 1) return ((const int*)p)[i] != 0;
  return ((const float*)p)[i] != 0.0f;
}
__global__ void detect_kernel(const unsigned char* __restrict__ p) {
  int big = 0, off = 0;
  for (int i = 0; i < 1024; ++i) {
    unsigned char c = p[i];
    big |= (c > 1) ? 1 : 0;
    off |= (c != 0 && (i & 3) != 0) ? 1 : 0;
  }
  g_flag = big ? 2 : (off ? 0 : 1);
}
__global__ void mask_kernel(const void* __restrict__ mp, const void* __restrict__ md,
                            float* __restrict__ outMP, float* __restrict__ outMD) {
  int f = g_flag;
  int idx = blockIdx.x * blockDim.x + threadIdx.x;
  if (idx < NB * GPNUM) {
    int b = idx / GPNUM, g = idx % GPNUM;
    int base = b * LP + g * 4;
    bool any = false;
#pragma unroll
    for (int r = 0; r < 4; ++r) any = any || read_mask(mp, base + r, f);
    g_masks[idx] = any ? 1 : 0;
    outMP[idx] = any ? 1.0f : 0.0f;
  } else {
    int j = idx - NB * GPNUM;
    if (j < NB * LDRG) {
      bool v = read_mask(md, j, f);
      g_masks[16384 + j] = v ? 1 : 0;
      outMD[j] = v ? 1.0f : 0.0f;
    }
  }
}

// ============== grouping + conversions (ILP x4) ==============
__global__ void group_bf16_v4(const float* __restrict__ P,
                              uint2* __restrict__ H, uint2* __restrict__ L) {
#pragma unroll
  for (int it = 0; it < 4; ++it) {
    int idx = blockIdx.x * 1024 + it * 256 + threadIdx.x;
    int d4 = idx & 127;
    int g = (idx >> 7) & 511;
    int b = idx >> 16;
    const float* p = P + ((size_t)b * LP + (size_t)g * 4) * DD + d4 * 4;
    float4 x0 = *(const float4*)p;
    float4 x1 = *(const float4*)(p + 512);
    float4 x2 = *(const float4*)(p + 1024);
    float4 x3 = *(const float4*)(p + 1536);
    float v0 = 0.25f * (x0.x + x1.x + x2.x + x3.x);
    float v1 = 0.25f * (x0.y + x1.y + x2.y + x3.y);
    float v2 = 0.25f * (x0.z + x1.z + x2.z + x3.z);
    float v3 = 0.25f * (x0.w + x1.w + x2.w + x3.w);
    uint32_t h01, l01, h23, l23;
    split2(v0, v1, h01, l01);
    split2(v2, v3, h23, l23);
    H[idx] = make_uint2(h01, h23);
    L[idx] = make_uint2(l01, l23);
  }
}

__global__ void cvt_bf16_v4(const float4* __restrict__ X, int n4,
                            uint2* __restrict__ H, uint2* __restrict__ L) {
#pragma unroll
  for (int it = 0; it < 4; ++it) {
    int i = blockIdx.x * 1024 + it * 256 + threadIdx.x;
    if (i >= n4) continue;
    float4 x = X[i];
    uint32_t h01, l01, h23, l23;
    split2(x.x, x.y, h01, l01);
    split2(x.z, x.w, h23, l23);
    H[i] = make_uint2(h01, h23);
    L[i] = make_uint2(l01, l23);
  }
}

__global__ void cvt_w6(const float4* w0, const float4* w1, const float4* w2,
                       const float4* w3, const float4* w4, const float4* w5,
                       uint2* __restrict__ H, uint2* __restrict__ L) {
  int wi = blockIdx.y;
  const float4* X = (wi == 0) ? w0 : (wi == 1) ? w1 : (wi == 2) ? w2
                   : (wi == 3) ? w3 : (wi == 4) ? w4 : w5;
#pragma unroll
  for (int it = 0; it < 4; ++it) {
    int i = blockIdx.x * 1024 + it * 256 + threadIdx.x;
    float4 x = X[i];
    uint32_t h01, l01, h23, l23;
    split2(x.x, x.y, h01, l01);
    split2(x.z, x.w, h23, l23);
    size_t o = (size_t)wi * 65536 + i;
    H[o] = make_uint2(h01, h23);
    L[o] = make_uint2(l01, l23);
  }
}

// ======================= MMA / ldmatrix macros =======================
#define MMA_BF16(c, a, b)                                                      \
  asm volatile("mma.sync.aligned.m16n8k16.row.col.f32.bf16.bf16.f32 "          \
               "{%0,%1,%2,%3}, {%4,%5,%6,%7}, {%8,%9}, {%0,%1,%2,%3};"         \
               : "+f"((c)[0]), "+f"((c)[1]), "+f"((c)[2]), "+f"((c)[3])        \
               : "r"((a)[0]), "r"((a)[1]), "r"((a)[2]), "r"((a)[3]),           \
                 "r"((b)[0]), "r"((b)[1]))

#define LDSM_X4(r0, r1, r2, r3, a)                                             \
  asm volatile("ldmatrix.sync.aligned.m8n8.x4.shared.b16 {%0,%1,%2,%3}, [%4];" \
               : "=r"(r0), "=r"(r1), "=r"(r2), "=r"(r3) : "r"(a))

#define LDSM_X4_T(r0, r1, r2, r3, a)                                           \
  asm volatile("ldmatrix.sync.aligned.m8n8.x4.trans.shared.b16 {%0,%1,%2,%3}, [%4];" \
               : "=r"(r0), "=r"(r1), "=r"(r2), "=r"(r3) : "r"(a))

// ====== bf16x3 projection (cp.async double-buffered, ALL 6 GEMMs merged) ======
// linear grid 4608: [0,3072) protein w0..w2, [3072,4608) drug w3..w5
#define PROJ_SMEM 61440
__global__ __launch_bounds__(256) void gemm_proj_mma(
    const u16* __restrict__ PGHp, const u16* __restrict__ PGLp,
    const u16* __restrict__ DRHp, const u16* __restrict__ DRLp,
    const u16* __restrict__ WHb, const u16* __restrict__ WLb,
    u16* __restrict__ OutBase) {
  extern __shared__ __align__(16) u16 dyn[];
  u16* AhB = dyn;
  u16* AlB = dyn + 10240;
  u16* BhB = dyn + 20480;
  u16* BlB = dyn + 25600;

  const int bid = blockIdx.x;
  int wi, x, y, loGap;
  size_t outOff;
  const u16 *Ah, *Al;
  if (bid < 3072) {
    wi = bid >> 10;
    int rem = bid & 1023;
    x = rem & 127; y = rem >> 7;
    Ah = PGHp; Al = PGLp;
    outOff = (size_t)wi * 16777216u;
    loGap = 8388608;
  } else {
    int b2 = bid - 3072;
    wi = 3 + (b2 >> 9);
    int rem = b2 & 511;
    x = rem & 63; y = rem >> 6;
    Ah = DRHp; Al = DRLp;
    outOff = 50331648u + (size_t)(wi - 3) * 8388608u;
    loGap = 4194304;
  }
  const u16* Wh = WHb + (size_t)wi * 262144;
  const u16* Wl = WLb + (size_t)wi * 262144;
  u16* Ch = OutBase + outOff;
  u16* Cl = Ch + loGap;
  const int mBase = x * 128;
  const int nBase = y * 64;

  const int tid = threadIdx.x;
  const int w = tid >> 5, lane = tid & 31;
  const int g = lane >> 2, t4 = lane & 3;
  const int wm = (w >> 1) * 32, wn = (w & 1) * 32;

  const int lane15 = lane & 15;
  const int hi8 = (lane >> 4) << 3;
  const uint32_t aAddrH = smaddr(AhB + (wm + lane15) * 40 + hi8);
  const uint32_t aAddrL = smaddr(AlB + (wm + lane15) * 40 + hi8);
  const int bn = (lane & 7) + hi8;
  const int bk = lane & 8;
  const uint32_t bAddrH = smaddr(BhB + (wn + bn) * 40 + bk);
  const uint32_t bAddrL = smaddr(BlB + (wn + bn) * 40 + bk);

  auto loadTile = [&](int k0, int buf) {
#pragma unroll
    for (int u = tid; u < 512; u += 256) {
      int row = u >> 2, seg = u & 3;
      size_t ga = (size_t)(mBase + row) * 512 + k0 + seg * 8;
      int so = buf * 5120 + row * 40 + seg * 8;
      CP16(smaddr(AhB + so), Ah + ga);
      CP16(smaddr(AlB + so), Al + ga);
    }
    {
      int row = tid >> 2, seg = tid & 3;
      size_t ga = (size_t)(nBase + row) * 512 + k0 + seg * 8;
      int so = buf * 2560 + row * 40 + seg * 8;
      CP16(smaddr(BhB + so), Wh + ga);
      CP16(smaddr(BlB + so), Wl + ga);
    }
    CP_COMMIT();
  };

  float acc[2][4][4];
#pragma unroll
  for (int mi = 0; mi < 2; ++mi)
#pragma unroll
    for (int j = 0; j < 4; ++j)
#pragma unroll
      for (int q = 0; q < 4; ++q) acc[mi][j][q] = 0.0f;

  loadTile(0, 0);
  for (int t = 0; t < 16; ++t) {
    if (t < 15) { loadTile((t + 1) * 32, (t + 1) & 1); CP_WAIT1(); }
    else CP_WAIT0();
    __syncthreads();
    const uint32_t aOff = (uint32_t)((t & 1) * 10240);
    const uint32_t bOff = (uint32_t)((t & 1) * 5120);
#pragma unroll
    for (int kk = 0; kk < 32; kk += 16) {
      uint32_t ah[2][4], al[2][4];
#pragma unroll
      for (int mi = 0; mi < 2; ++mi) {
        LDSM_X4(ah[mi][0], ah[mi][1], ah[mi][2], ah[mi][3], aAddrH + aOff + (mi * 640 + kk) * 2);
        LDSM_X4(al[mi][0], al[mi][1], al[mi][2], al[mi][3], aAddrL + aOff + (mi * 640 + kk) * 2);
      }
      uint32_t bh[4][2], bl[4][2];
#pragma unroll
      for (int p = 0; p < 2; ++p) {
        LDSM_X4(bh[2 * p][0], bh[2 * p][1], bh[2 * p + 1][0], bh[2 * p + 1][1],
                bAddrH + bOff + (p * 640 + kk) * 2);
        LDSM_X4(bl[2 * p][0], bl[2 * p][1], bl[2 * p + 1][0], bl[2 * p + 1][1],
                bAddrL + bOff + (p * 640 + kk) * 2);
      }
#pragma unroll
      for (int mi = 0; mi < 2; ++mi)
#pragma unroll
        for (int j = 0; j < 4; ++j) {
          MMA_BF16(acc[mi][j], ah[mi], bh[j]);
          MMA_BF16(acc[mi][j], ah[mi], bl[j]);
          MMA_BF16(acc[mi][j], al[mi], bh[j]);
        }
    }
    __syncthreads();
  }

#pragma unroll
  for (int mi = 0; mi < 2; ++mi) {
    int row = mBase + wm + mi * 16 + g;
#pragma unroll
    for (int j = 0; j < 4; ++j) {
      int col = nBase + wn + j * 8 + t4 * 2;
      uint32_t hi, lo;
      split2(acc[mi][j][0], acc[mi][j][1], hi, lo);
      *(uint32_t*)(Ch + (size_t)row * 512 + col) = hi;
      *(uint32_t*)(Cl + (size_t)row * 512 + col) = lo;
      split2(acc[mi][j][2], acc[mi][j][3], hi, lo);
      *(uint32_t*)(Ch + (size_t)(row + 8) * 512 + col) = hi;
      *(uint32_t*)(Cl + (size_t)(row + 8) * 512 + col) = lo;
    }
  }
}

// ====== bf16x3 logits (cp.async, T=2, BOTH directions merged): masked fp32 out ======
// linear grid 8192: [0,4096) dir1 (Lq512,Lk256), [4096,8192) dir2 (Lq256,Lk512)
#define LOGITS_SMEM 61440
__global__ __launch_bounds__(256) void gemm_logits_mma(
    float* __restrict__ sc, const unsigned char* __restrict__ mg) {
  extern __shared__ __align__(16) u16 dyn[];
  u16* AhB = dyn;
  u16* AlB = dyn + 10240;
  u16* BhB = dyn + 20480;
  u16* BlB = dyn + 25600;

  const int bid = blockIdx.x;
  int Lq, Lk, x, y, z;
  const u16 *Qh, *Ql, *Kh, *Kl;
  float* Sd;
  const unsigned char *mqB, *mkB;
  if (bid < 4096) {
    Lq = 512; Lk = 256;
    x = bid & 3; y = (bid >> 2) & 3; z = bid >> 4;
    Qh = (const u16*)(sc + 33554432); Ql = (const u16*)(sc + 37748736);
    Kh = (const u16*)(sc + 62914560); Kl = (const u16*)(sc + 65011712);
    Sd = sc;
    mqB = mg; mkB = mg + 16384;
  } else {
    int rem = bid - 4096;
    Lq = 256; Lk = 512;
    x = rem & 1; y = (rem >> 1) & 7; z = rem >> 4;
    Qh = (const u16*)(sc + 58720256); Ql = (const u16*)(sc + 60817408);
    Kh = (const u16*)(sc + 41943040); Kl = (const u16*)(sc + 46137344);
    Sd = sc + 85458944;
    mqB = mg + 16384; mkB = mg;
  }
  const int tid = threadIdx.x;
  const int w = tid >> 5, lane = tid & 31;
  const int g = lane >> 2, t4 = lane & 3;
  const int wm = (w >> 1) * 32, wn = (w & 1) * 32;
  const int mBase = x * 128;
  const int nBase = y * 64;
  const int b = z >> 3, h = z & 7;
  const u16* Ahg = Qh + (size_t)b * Lq * 512 + h * 64;
  const u16* Alg = Ql + (size_t)b * Lq * 512 + h * 64;
  const u16* Bhg = Kh + (size_t)b * Lk * 512 + h * 64;
  const u16* Blg = Kl + (size_t)b * Lk * 512 + h * 64;
  float* C = Sd + (size_t)z * Lq * Lk;
  const unsigned char* mqb = mqB + b * Lq;
  const unsigned char* mkb = mkB + b * Lk;

  const int lane15 = lane & 15;
  const int hi8 = (lane >> 4) << 3;
  const uint32_t aAddrH = smaddr(AhB + (wm + lane15) * 40 + hi8);
  const uint32_t aAddrL = smaddr(AlB + (wm + lane15) * 40 + hi8);
  const int bn = (lane & 7) + hi8;
  const int bk = lane & 8;
  const uint32_t bAddrH = smaddr(BhB + (wn + bn) * 40 + bk);
  const uint32_t bAddrL = smaddr(BlB + (wn + bn) * 40 + bk);

  auto loadTile = [&](int k0, int buf) {
#pragma unroll
    for (int u = tid; u < 512; u += 256) {
      int row = u >> 2, seg = u & 3;
      size_t ga = (size_t)(mBase + row) * 512 + k0 + seg * 8;
      int so = buf * 5120 + row * 40 + seg * 8;
      CP16(smaddr(AhB + so), Ahg + ga);
      CP16(smaddr(AlB + so), Alg + ga);
    }
    {
      int row = tid >> 2, seg = tid & 3;
      size_t ga = (size_t)(nBase + row) * 512 + k0 + seg * 8;
      int so = buf * 2560 + row * 40 + seg * 8;
      CP16(smaddr(BhB + so), Bhg + ga);
      CP16(smaddr(BlB + so), Blg + ga);
    }
    CP_COMMIT();
  };

  float acc[2][4][4];
#pragma unroll
  for (int mi = 0; mi < 2; ++mi)
#pragma unroll
    for (int j = 0; j < 4; ++j)
#pragma unroll
      for (int q = 0; q < 4; ++q) acc[mi][j][q] = 0.0f;

  loadTile(0, 0);
#pragma unroll
  for (int t = 0; t < 2; ++t) {
    if (t < 1) { loadTile(32, 1); CP_WAIT1(); }
    else CP_WAIT0();
    __syncthreads();
    const uint32_t aOff = (uint32_t)(t * 10240);
    const uint32_t bOff = (uint32_t)(t * 5120);
#pragma unroll
    for (int kk = 0; kk < 32; kk += 16) {
      uint32_t ah[2][4], al[2][4];
#pragma unroll
      for (int mi = 0; mi < 2; ++mi) {
        LDSM_X4(ah[mi][0], ah[mi][1], ah[mi][2], ah[mi][3], aAddrH + aOff + (mi * 640 + kk) * 2);
        LDSM_X4(al[mi][0], al[mi][1], al[mi][2], al[mi][3], aAddrL + aOff + (mi * 640 + kk) * 2);
      }
      uint32_t bh[4][2], bl[4][2];
#pragma unroll
      for (int p = 0; p < 2; ++p) {
        LDSM_X4(bh[2 * p][0], bh[2 * p][1], bh[2 * p + 1][0], bh[2 * p + 1][1],
                bAddrH + bOff + (p * 640 + kk) * 2);
        LDSM_X4(bl[2 * p][0], bl[2 * p][1], bl[2 * p + 1][0], bl[2 * p + 1][1],
                bAddrL + bOff + (p * 640 + kk) * 2);
      }
#pragma unroll
      for (int mi = 0; mi < 2; ++mi)
#pragma unroll
        for (int j = 0; j < 4; ++j) {
          MMA_BF16(acc[mi][j], ah[mi], bh[j]);
          MMA_BF16(acc[mi][j], ah[mi], bl[j]);
          MMA_BF16(acc[mi][j], al[mi], bh[j]);
        }
    }
    __syncthreads();
  }

#pragma unroll
  for (int mi = 0; mi < 2; ++mi) {
    int row = mBase + wm + mi * 16 + g;
    float p0 = mqb[row] ? 0.0f : 1.0e6f;
    float p1 = mqb[row + 8] ? 0.0f : 1.0e6f;
#pragma unroll
    for (int j = 0; j < 4; ++j) {
      int col = nBase + wn + j * 8 + t4 * 2;
      float c0 = mkb[col] ? 0.0f : 1.0e6f;
      float c1 = mkb[col + 1] ? 0.0f : 1.0e6f;
      *(float2*)(C + (size_t)row * Lk + col) =
          make_float2(acc[mi][j][0] - fmaxf(p0, c0), acc[mi][j][1] - fmaxf(p0, c1));
      *(float2*)(C + (size_t)(row + 8) * Lk + col) =
          make_float2(acc[mi][j][2] - fmaxf(p1, c0), acc[mi][j][3] - fmaxf(p1, c1));
    }
  }
}

// ---------------- softmax: fp32 in S -> alpha fp32 out + bf16 hi/lo in-place ----------------
template <int LK>
__global__ __launch_bounds__(256) void softmax_kernel(
    float* __restrict__ S, const unsigned char* __restrict__ mq,
    float* __restrict__ alphaOut, int Lq) {
  __shared__ float sbuf[8][LK + 1];
  const int l = blockIdx.x, b = blockIdx.y;
  const int tid = threadIdx.x, w = tid >> 5, lane = tid & 31;
  const size_t abase = ((size_t)b * Lq + l) * (size_t)(LK * 8);

  if (!mq[b * Lq + l]) {
    for (int idx = tid; idx < LK * 8; idx += 256) alphaOut[abase + idx] = 0.0f;
#pragma unroll
    for (int h = 0; h < 8; ++h) {
      float* srow = S + ((size_t)(b * 8 + h) * Lq + l) * LK;
      for (int k = tid; k < LK; k += 256) srow[k] = 0.0f;
    }
    return;
  }

  float* srow = S + ((size_t)(b * 8 + w) * Lq + l) * LK;
  const int nit = LK / 32;
  float v[LK / 32];
  float mx = -3.0e38f;
#pragma unroll
  for (int i = 0; i < nit; ++i) { v[i] = srow[lane + 32 * i]; mx = fmaxf(mx, v[i]); }
#pragma unroll
  for (int o = 16; o > 0; o >>= 1) mx = fmaxf(mx, __shfl_xor_sync(0xffffffffu, mx, o));
  float sum = 0.0f;
#pragma unroll
  for (int i = 0; i < nit; ++i) { float e = __expf(v[i] - mx); v[i] = e; sum += e; }
#pragma unroll
  for (int o = 16; o > 0; o >>= 1) sum += __shfl_xor_sync(0xffffffffu, sum, o);
  float inv = 1.0f / sum;
  u16* arow = (u16*)srow;
#pragma unroll
  for (int i = 0; i < nit; ++i) {
    float a = v[i] * inv;
    sbuf[w][lane + 32 * i] = a;
    u16 hb = bf16bits(a);
    arow[lane + 32 * i] = hb;
    arow[LK + lane + 32 * i] = bf16bits(a - bf16val(hb));
  }
  __syncthreads();
#pragma unroll 4
  for (int idx = tid; idx < LK * 8; idx += 256) {
    int k = idx >> 3, h = idx & 7;
    alphaOut[abase + idx] = sbuf[h][k];
  }
}

// ====== bf16x3 AV (cp.async double-buffered, BOTH directions merged) ======
// linear grid 1536: [0,1024) dir1, [1024,1536) dir2
#define AV_SMEM 59392
__global__ __launch_bounds__(256) void gemm_av_mma(
    float* __restrict__ sc, float* __restrict__ out) {
  extern __shared__ __align__(16) u16 dyn[];
  u16* AhB = dyn;
  u16* AlB = dyn + 10240;
  u16* BhB = dyn + 20480;
  u16* BlB = dyn + 25088;

  const int bid = blockIdx.x;
  int Lq, Lk, x, z;
  const float* Sd;
  const u16 *Vh, *Vl;
  float* OutD;
  if (bid < 1024) {
    Lq = 512; Lk = 256;
    x = bid & 3; z = bid >> 2;
    Sd = sc;
    Vh = (const u16*)(sc + 67108864); Vl = (const u16*)(sc + 69206016);
    OutD = out;
  } else {
    int rem = bid - 1024;
    Lq = 256; Lk = 512;
    x = rem & 1; z = rem >> 1;
    Sd = sc + 85458944;
    Vh = (const u16*)(sc + 50331648); Vl = (const u16*)(sc + 54525952);
    OutD = out + 8388608;
  }
  const int tid = threadIdx.x;
  const int w = tid >> 5, lane = tid & 31;
  const int g = lane >> 2, t4 = lane & 3;
  const int wm = (w >> 1) * 32, wn = (w & 1) * 32;
  const int mBase = x * 128;
  const int b = z >> 3, h = z & 7;
  const u16* Abase = (const u16*)(Sd + (size_t)z * Lq * Lk);
  const size_t vbase = (size_t)b * Lk * 512 + h * 64;
  float* C = OutD + (size_t)b * Lq * 512 + h * 64;

  const int lane15 = lane & 15;
  const int hi8 = (lane >> 4) << 3;
  const uint32_t aAddrH = smaddr(AhB + (wm + lane15) * 40 + hi8);
  const uint32_t aAddrL = smaddr(AlB + (wm + lane15) * 40 + hi8);
  const int bkOff = (lane & 7) + (lane & 8);
  const uint32_t bAddrH = smaddr(BhB + bkOff * 72 + wn + hi8);
  const uint32_t bAddrL = smaddr(BlB + bkOff * 72 + wn + hi8);

  auto loadTile = [&](int k0, int buf) {
#pragma unroll
    for (int u = tid; u < 512; u += 256) {
      int row = u >> 2, seg = u & 3;
      const u16* ar = Abase + (size_t)(mBase + row) * 2 * Lk + k0 + seg * 8;
      int so = buf * 5120 + row * 40 + seg * 8;
      CP16(smaddr(AhB + so), ar);
      CP16(smaddr(AlB + so), ar + Lk);
    }
    {
      int row = tid >> 3, seg = tid & 7;
      size_t ga = vbase + (size_t)(k0 + row) * 512 + seg * 8;
      int so = buf * 2304 + row * 72 + seg * 8;
      CP16(smaddr(BhB + so), Vh + ga);
      CP16(smaddr(BlB + so), Vl + ga);
    }
    CP_COMMIT();
  };

  float acc[2][4][4];
#pragma unroll
  for (int mi = 0; mi < 2; ++mi)
#pragma unroll
    for (int j = 0; j < 4; ++j)
#pragma unroll
      for (int q = 0; q < 4; ++q) acc[mi][j][q] = 0.0f;

  const int T = Lk / 32;
  loadTile(0, 0);
  for (int t = 0; t < T; ++t) {
    if (t < T - 1) { loadTile((t + 1) * 32, (t + 1) & 1); CP_WAIT1(); }
    else CP_WAIT0();
    __syncthreads();
    const uint32_t aOff = (uint32_t)((t & 1) * 10240);
    const uint32_t bOff = (uint32_t)((t & 1) * 4608);
#pragma unroll
    for (int kk = 0; kk < 32; kk += 16) {
      uint32_t ah[2][4], al[2][4];
#pragma unroll
      for (int mi = 0; mi < 2; ++mi) {
        LDSM_X4(ah[mi][0], ah[mi][1], ah[mi][2], ah[mi][3], aAddrH + aOff + (mi * 640 + kk) * 2);
        LDSM_X4(al[mi][0], al[mi][1], al[mi][2], al[mi][3], aAddrL + aOff + (mi * 640 + kk) * 2);
      }
      uint32_t bh[4][2], bl[4][2];
#pragma unroll
      for (int p = 0; p < 2; ++p) {
        LDSM_X4_T(bh[2 * p][0], bh[2 * p][1], bh[2 * p + 1][0], bh[2 * p + 1][1],
                  bAddrH + bOff + (kk * 72 + p * 16) * 2);
        LDSM_X4_T(bl[2 * p][0], bl[2 * p][1], bl[2 * p + 1][0], bl[2 * p + 1][1],
                  bAddrL + bOff + (kk * 72 + p * 16) * 2);
      }
#pragma unroll
      for (int mi = 0; mi < 2; ++mi)
#pragma unroll
        for (int j = 0; j < 4; ++j) {
          MMA_BF16(acc[mi][j], ah[mi], bh[j]);
          MMA_BF16(acc[mi][j], ah[mi], bl[j]);
          MMA_BF16(acc[mi][j], al[mi], bh[j]);
        }
    }
    __syncthreads();
  }

#pragma unroll
  for (int mi = 0; mi < 2; ++mi) {
    int row = mBase + wm + mi * 16 + g;
#pragma unroll
    for (int j = 0; j < 4; ++j) {
      int col = wn + j * 8 + t4 * 2;
      *(float2*)(C + (size_t)row * 512 + col) = make_float2(acc[mi][j][0], acc[mi][j][1]);
      *(float2*)(C + (size_t)(row + 8) * 512 + col) = make_float2(acc[mi][j][2], acc[mi][j][3]);
    }
  }
}

// ---------------- launch ----------------
extern "C" void kernel_launch(void* const* d_in, const int* in_sizes, int n_in,
                              void* d_out, int out_size) {
  const float* protein = (const float*)d_in[0];
  const float* drug    = (const float*)d_in[1];
  const void*  mpraw   = d_in[2];
  const void*  mdraw   = d_in[3];
  const float* W[6] = {(const float*)d_in[4], (const float*)d_in[5], (const float*)d_in[6],
                       (const float*)d_in[7], (const float*)d_in[8], (const float*)d_in[9]};
  float* out = (float*)d_out;

  float* sc = nullptr;
  cudaGetSymbolAddress((void**)&sc, g_scratch);
  unsigned char* mg = nullptr;
  cudaGetSymbolAddress((void**)&mg, g_masks);

  float* S1 = sc;
  float* S2 = sc + 85458944;
  u16* QPh = (u16*)(sc + 33554432);
  u16* PGH = (u16*)(sc + 71303168); u16* PGL = (u16*)(sc + 75497472);
  u16* DRH = (u16*)(sc + 79691776); u16* DRL = (u16*)(sc + 81788928);
  u16* WHb = (u16*)(sc + 83886080); u16* WLb = (u16*)(sc + 84672512);
  unsigned char* mpg = mg;
  unsigned char* mdg = mg + 16384;

  const size_t OFF_MP   = 12582912;
  const size_t OFF_MD   = 12599296;
  const size_t OFF_APD  = 12607488;
  const size_t OFF_ADP  = 46161920;

  static int attr_done = 0;
  if (!attr_done) {
    cudaFuncSetAttribute(gemm_proj_mma, cudaFuncAttributeMaxDynamicSharedMemorySize, PROJ_SMEM);
    cudaFuncSetAttribute(gemm_logits_mma, cudaFuncAttributeMaxDynamicSharedMemorySize, LOGITS_SMEM);
    cudaFuncSetAttribute(gemm_av_mma, cudaFuncAttributeMaxDynamicSharedMemorySize, AV_SMEM);
    attr_done = 1;
  }

  detect_kernel<<<1, 1>>>((const unsigned char*)mpraw);
  mask_kernel<<<96, 256>>>(mpraw, mdraw, out + OFF_MP, out + OFF_MD);
  group_bf16_v4<<<2048, 256>>>(protein, (uint2*)PGH, (uint2*)PGL);
  cvt_bf16_v4<<<1024, 256>>>((const float4*)drug, 1048576, (uint2*)DRH, (uint2*)DRL);
  cvt_w6<<<dim3(64, 6), 256>>>((const float4*)W[0], (const float4*)W[1], (const float4*)W[2],
                               (const float4*)W[3], (const float4*)W[4], (const float4*)W[5],
                               (uint2*)WHb, (uint2*)WLb);

  // all 6 projections in one launch
  gemm_proj_mma<<<4608, 256, PROJ_SMEM>>>(PGH, PGL, DRH, DRL, WHb, WLb, QPh);

  // both logits directions in one launch (dir1 -> S1, dir2 -> S2)
  gemm_logits_mma<<<8192, 256, LOGITS_SMEM>>>(sc, mg);

  softmax_kernel<256><<<dim3(512, 32), 256>>>(S1, mpg, out + OFF_APD, 512);
  softmax_kernel<512><<<dim3(256, 32), 256>>>(S2, mdg, out + OFF_ADP, 256);

  // both AV directions in one launch
  gemm_av_mma<<<1536, 256, AV_SMEM>>>(sc, out);

  (void)in_sizes; (void)n_in; (void)out_size;
}

// round 15
// speedup vs baseline: 1.1117x; 1.0104x over previous
#include <cuda_runtime.h>
#include <cuda_bf16.h>
#include <cstdint>

#define NB    32
#define LP    2048
#define LDRG  256
#define DD    512
#define GPNUM 512

typedef unsigned short u16;

// ======================= scratch (floats) =======================
// S1 @0 (33554432), Q/K/V bf16 @33554432.., PG/DR/W @71303168.., S2 @85458944
__device__ float g_scratch[119013376];
__device__ unsigned char g_masks[24576];
__device__ int g_flag;

__device__ __forceinline__ u16 bf16bits(float x) {
  __nv_bfloat16 h = __float2bfloat16_rn(x);
  return *reinterpret_cast<u16*>(&h);
}
__device__ __forceinline__ float bf16val(u16 b) {
  __nv_bfloat16 h = *reinterpret_cast<__nv_bfloat16*>(&b);
  return __bfloat162float(h);
}
__device__ __forceinline__ void split2(float v0, float v1, uint32_t& hi, uint32_t& lo) {
  u16 h0 = bf16bits(v0), h1 = bf16bits(v1);
  u16 l0 = bf16bits(v0 - bf16val(h0)), l1 = bf16bits(v1 - bf16val(h1));
  hi = (uint32_t)h0 | ((uint32_t)h1 << 16);
  lo = (uint32_t)l0 | ((uint32_t)l1 << 16);
}
__device__ __forceinline__ uint32_t smaddr(const void* p) {
  return (uint32_t)__cvta_generic_to_shared(p);
}

#define CP16(s, g) \
  asm volatile("cp.async.cg.shared.global [%0], [%1], 16;" :: "r"(s), "l"(g))
#define CP_COMMIT() asm volatile("cp.async.commit_group;" ::: "memory")
#define CP_WAIT0() asm volatile("cp.async.wait_group 0;" ::: "memory")
#define CP_WAIT1() asm volatile("cp.async.wait_group 1;" ::: "memory")

// ======================= masks / detect =======================
__device__ __forceinline__ bool read_mask(const void* p, int i, int f) {
  if (f == 0) return ((const unsigned char*)p)[i] != 0;
  if (f == 1) return ((const int*)p)[i] != 0;
  return ((const float*)p)[i] != 0.0f;
}
__global__ void detect_kernel(const unsigned char* __restrict__ p) {
  int big = 0, off = 0;
  for (int i = 0; i < 1024; ++i) {
    unsigned char c = p[i];
    big |= (c > 1) ? 1 : 0;
    off |= (c != 0 && (i & 3) != 0) ? 1 : 0;
  }
  g_flag = big ? 2 : (off ? 0 : 1);
}

// ====== merged pre-processing: group + drug cvt + weight cvt + masks ======
// grid 3552: [0,2048) group, [2048,3072) drug, [3072,3456) weights, [3456,3552) masks
__global__ void prep_all(const float* __restrict__ P, const float* __restrict__ Dr,
                         const float4* w0, const float4* w1, const float4* w2,
                         const float4* w3, const float4* w4, const float4* w5,
                         const void* __restrict__ mpraw, const void* __restrict__ mdraw,
                         uint2* __restrict__ PGHp, uint2* __restrict__ PGLp,
                         uint2* __restrict__ DRHp, uint2* __restrict__ DRLp,
                         uint2* __restrict__ WHp, uint2* __restrict__ WLp,
                         float* __restrict__ outMP, float* __restrict__ outMD) {
  const int bid = blockIdx.x;
  const int tid = threadIdx.x;
  if (bid < 2048) {
#pragma unroll
    for (int it = 0; it < 4; ++it) {
      int idx = bid * 1024 + it * 256 + tid;
      int d4 = idx & 127;
      int g = (idx >> 7) & 511;
      int b = idx >> 16;
      const float* p = P + ((size_t)b * LP + (size_t)g * 4) * DD + d4 * 4;
      float4 x0 = *(const float4*)p;
      float4 x1 = *(const float4*)(p + 512);
      float4 x2 = *(const float4*)(p + 1024);
      float4 x3 = *(const float4*)(p + 1536);
      float v0 = 0.25f * (x0.x + x1.x + x2.x + x3.x);
      float v1 = 0.25f * (x0.y + x1.y + x2.y + x3.y);
      float v2 = 0.25f * (x0.z + x1.z + x2.z + x3.z);
      float v3 = 0.25f * (x0.w + x1.w + x2.w + x3.w);
      uint32_t h01, l01, h23, l23;
      split2(v0, v1, h01, l01);
      split2(v2, v3, h23, l23);
      PGHp[idx] = make_uint2(h01, h23);
      PGLp[idx] = make_uint2(l01, l23);
    }
  } else if (bid < 3072) {
    int b2 = bid - 2048;
    const float4* X = (const float4*)Dr;
#pragma unroll
    for (int it = 0; it < 4; ++it) {
      int i = b2 * 1024 + it * 256 + tid;   // < 1048576
      float4 x = X[i];
      uint32_t h01, l01, h23, l23;
      split2(x.x, x.y, h01, l01);
      split2(x.z, x.w, h23, l23);
      DRHp[i] = make_uint2(h01, h23);
      DRLp[i] = make_uint2(l01, l23);
    }
  } else if (bid < 3456) {
    int b3 = bid - 3072;
    int wi = b3 >> 6, xb = b3 & 63;
    const float4* X = (wi == 0) ? w0 : (wi == 1) ? w1 : (wi == 2) ? w2
                     : (wi == 3) ? w3 : (wi == 4) ? w4 : w5;
#pragma unroll
    for (int it = 0; it < 4; ++it) {
      int i = xb * 1024 + it * 256 + tid;   // < 65536
      float4 x = X[i];
      uint32_t h01, l01, h23, l23;
      split2(x.x, x.y, h01, l01);
      split2(x.z, x.w, h23, l23);
      size_t o = (size_t)wi * 65536 + i;
      WHp[o] = make_uint2(h01, h23);
      WLp[o] = make_uint2(l01, l23);
    }
  } else {
    int f = g_flag;
    int idx = (bid - 3456) * 256 + tid;
    if (idx < NB * GPNUM) {
      int b = idx / GPNUM, g = idx % GPNUM;
      int base = b * LP + g * 4;
      bool any = false;
#pragma unroll
      for (int r = 0; r < 4; ++r) any = any || read_mask(mpraw, base + r, f);
      g_masks[idx] = any ? 1 : 0;
      outMP[idx] = any ? 1.0f : 0.0f;
    } else {
      int j = idx - NB * GPNUM;
      if (j < NB * LDRG) {
        bool v = read_mask(mdraw, j, f);
        g_masks[16384 + j] = v ? 1 : 0;
        outMD[j] = v ? 1.0f : 0.0f;
      }
    }
  }
}

// ======================= MMA / ldmatrix macros =======================
#define MMA_BF16(c, a, b)                                                      \
  asm volatile("mma.sync.aligned.m16n8k16.row.col.f32.bf16.bf16.f32 "          \
               "{%0,%1,%2,%3}, {%4,%5,%6,%7}, {%8,%9}, {%0,%1,%2,%3};"         \
               : "+f"((c)[0]), "+f"((c)[1]), "+f"((c)[2]), "+f"((c)[3])        \
               : "r"((a)[0]), "r"((a)[1]), "r"((a)[2]), "r"((a)[3]),           \
                 "r"((b)[0]), "r"((b)[1]))

#define LDSM_X4(r0, r1, r2, r3, a)                                             \
  asm volatile("ldmatrix.sync.aligned.m8n8.x4.shared.b16 {%0,%1,%2,%3}, [%4];" \
               : "=r"(r0), "=r"(r1), "=r"(r2), "=r"(r3) : "r"(a))

#define LDSM_X4_T(r0, r1, r2, r3, a)                                           \
  asm volatile("ldmatrix.sync.aligned.m8n8.x4.trans.shared.b16 {%0,%1,%2,%3}, [%4];" \
               : "=r"(r0), "=r"(r1), "=r"(r2), "=r"(r3) : "r"(a))

// ====== bf16x3 projection (cp.async double-buffered, ALL 6 GEMMs merged) ======
#define PROJ_SMEM 61440
__global__ __launch_bounds__(256) void gemm_proj_mma(
    const u16* __restrict__ PGHp, const u16* __restrict__ PGLp,
    const u16* __restrict__ DRHp, const u16* __restrict__ DRLp,
    const u16* __restrict__ WHb, const u16* __restrict__ WLb,
    u16* __restrict__ OutBase) {
  extern __shared__ __align__(16) u16 dyn[];
  u16* AhB = dyn;
  u16* AlB = dyn + 10240;
  u16* BhB = dyn + 20480;
  u16* BlB = dyn + 25600;

  const int bid = blockIdx.x;
  int wi, x, y, loGap;
  size_t outOff;
  const u16 *Ah, *Al;
  if (bid < 3072) {
    wi = bid >> 10;
    int rem = bid & 1023;
    x = rem & 127; y = rem >> 7;
    Ah = PGHp; Al = PGLp;
    outOff = (size_t)wi * 16777216u;
    loGap = 8388608;
  } else {
    int b2 = bid - 3072;
    wi = 3 + (b2 >> 9);
    int rem = b2 & 511;
    x = rem & 63; y = rem >> 6;
    Ah = DRHp; Al = DRLp;
    outOff = 50331648u + (size_t)(wi - 3) * 8388608u;
    loGap = 4194304;
  }
  const u16* Wh = WHb + (size_t)wi * 262144;
  const u16* Wl = WLb + (size_t)wi * 262144;
  u16* Ch = OutBase + outOff;
  u16* Cl = Ch + loGap;
  const int mBase = x * 128;
  const int nBase = y * 64;

  const int tid = threadIdx.x;
  const int w = tid >> 5, lane = tid & 31;
  const int g = lane >> 2, t4 = lane & 3;
  const int wm = (w >> 1) * 32, wn = (w & 1) * 32;

  const int lane15 = lane & 15;
  const int hi8 = (lane >> 4) << 3;
  const uint32_t aAddrH = smaddr(AhB + (wm + lane15) * 40 + hi8);
  const uint32_t aAddrL = smaddr(AlB + (wm + lane15) * 40 + hi8);
  const int bn = (lane & 7) + hi8;
  const int bk = lane & 8;
  const uint32_t bAddrH = smaddr(BhB + (wn + bn) * 40 + bk);
  const uint32_t bAddrL = smaddr(BlB + (wn + bn) * 40 + bk);

  auto loadTile = [&](int k0, int buf) {
#pragma unroll
    for (int u = tid; u < 512; u += 256) {
      int row = u >> 2, seg = u & 3;
      size_t ga = (size_t)(mBase + row) * 512 + k0 + seg * 8;
      int so = buf * 5120 + row * 40 + seg * 8;
      CP16(smaddr(AhB + so), Ah + ga);
      CP16(smaddr(AlB + so), Al + ga);
    }
    {
      int row = tid >> 2, seg = tid & 3;
      size_t ga = (size_t)(nBase + row) * 512 + k0 + seg * 8;
      int so = buf * 2560 + row * 40 + seg * 8;
      CP16(smaddr(BhB + so), Wh + ga);
      CP16(smaddr(BlB + so), Wl + ga);
    }
    CP_COMMIT();
  };

  float acc[2][4][4];
#pragma unroll
  for (int mi = 0; mi < 2; ++mi)
#pragma unroll
    for (int j = 0; j < 4; ++j)
#pragma unroll
      for (int q = 0; q < 4; ++q) acc[mi][j][q] = 0.0f;

  loadTile(0, 0);
  for (int t = 0; t < 16; ++t) {
    if (t < 15) { loadTile((t + 1) * 32, (t + 1) & 1); CP_WAIT1(); }
    else CP_WAIT0();
    __syncthreads();
    const uint32_t aOff = (uint32_t)((t & 1) * 10240);
    const uint32_t bOff = (uint32_t)((t & 1) * 5120);
#pragma unroll
    for (int kk = 0; kk < 32; kk += 16) {
      uint32_t ah[2][4], al[2][4];
#pragma unroll
      for (int mi = 0; mi < 2; ++mi) {
        LDSM_X4(ah[mi][0], ah[mi][1], ah[mi][2], ah[mi][3], aAddrH + aOff + (mi * 640 + kk) * 2);
        LDSM_X4(al[mi][0], al[mi][1], al[mi][2], al[mi][3], aAddrL + aOff + (mi * 640 + kk) * 2);
      }
      uint32_t bh[4][2], bl[4][2];
#pragma unroll
      for (int p = 0; p < 2; ++p) {
        LDSM_X4(bh[2 * p][0], bh[2 * p][1], bh[2 * p + 1][0], bh[2 * p + 1][1],
                bAddrH + bOff + (p * 640 + kk) * 2);
        LDSM_X4(bl[2 * p][0], bl[2 * p][1], bl[2 * p + 1][0], bl[2 * p + 1][1],
                bAddrL + bOff + (p * 640 + kk) * 2);
      }
#pragma unroll
      for (int mi = 0; mi < 2; ++mi)
#pragma unroll
        for (int j = 0; j < 4; ++j) {
          MMA_BF16(acc[mi][j], ah[mi], bh[j]);
          MMA_BF16(acc[mi][j], ah[mi], bl[j]);
          MMA_BF16(acc[mi][j], al[mi], bh[j]);
        }
    }
    __syncthreads();
  }

#pragma unroll
  for (int mi = 0; mi < 2; ++mi) {
    int row = mBase + wm + mi * 16 + g;
#pragma unroll
    for (int j = 0; j < 4; ++j) {
      int col = nBase + wn + j * 8 + t4 * 2;
      uint32_t hi, lo;
      split2(acc[mi][j][0], acc[mi][j][1], hi, lo);
      *(uint32_t*)(Ch + (size_t)row * 512 + col) = hi;
      *(uint32_t*)(Cl + (size_t)row * 512 + col) = lo;
      split2(acc[mi][j][2], acc[mi][j][3], hi, lo);
      *(uint32_t*)(Ch + (size_t)(row + 8) * 512 + col) = hi;
      *(uint32_t*)(Cl + (size_t)(row + 8) * 512 + col) = lo;
    }
  }
}

// ====== bf16x3 logits (cp.async, T=2, BOTH directions merged): masked fp32 out ======
#define LOGITS_SMEM 61440
__global__ __launch_bounds__(256) void gemm_logits_mma(
    float* __restrict__ sc, const unsigned char* __restrict__ mg) {
  extern __shared__ __align__(16) u16 dyn[];
  u16* AhB = dyn;
  u16* AlB = dyn + 10240;
  u16* BhB = dyn + 20480;
  u16* BlB = dyn + 25600;

  const int bid = blockIdx.x;
  int Lq, Lk, x, y, z;
  const u16 *Qh, *Ql, *Kh, *Kl;
  float* Sd;
  const unsigned char *mqB, *mkB;
  if (bid < 4096) {
    Lq = 512; Lk = 256;
    x = bid & 3; y = (bid >> 2) & 3; z = bid >> 4;
    Qh = (const u16*)(sc + 33554432); Ql = (const u16*)(sc + 37748736);
    Kh = (const u16*)(sc + 62914560); Kl = (const u16*)(sc + 65011712);
    Sd = sc;
    mqB = mg; mkB = mg + 16384;
  } else {
    int rem = bid - 4096;
    Lq = 256; Lk = 512;
    x = rem & 1; y = (rem >> 1) & 7; z = rem >> 4;
    Qh = (const u16*)(sc + 58720256); Ql = (const u16*)(sc + 60817408);
    Kh = (const u16*)(sc + 41943040); Kl = (const u16*)(sc + 46137344);
    Sd = sc + 85458944;
    mqB = mg + 16384; mkB = mg;
  }
  const int tid = threadIdx.x;
  const int w = tid >> 5, lane = tid & 31;
  const int g = lane >> 2, t4 = lane & 3;
  const int wm = (w >> 1) * 32, wn = (w & 1) * 32;
  const int mBase = x * 128;
  const int nBase = y * 64;
  const int b = z >> 3, h = z & 7;
  const u16* Ahg = Qh + (size_t)b * Lq * 512 + h * 64;
  const u16* Alg = Ql + (size_t)b * Lq * 512 + h * 64;
  const u16* Bhg = Kh + (size_t)b * Lk * 512 + h * 64;
  const u16* Blg = Kl + (size_t)b * Lk * 512 + h * 64;
  float* C = Sd + (size_t)z * Lq * Lk;
  const unsigned char* mqb = mqB + b * Lq;
  const unsigned char* mkb = mkB + b * Lk;

  const int lane15 = lane & 15;
  const int hi8 = (lane >> 4) << 3;
  const uint32_t aAddrH = smaddr(AhB + (wm + lane15) * 40 + hi8);
  const uint32_t aAddrL = smaddr(AlB + (wm + lane15) * 40 + hi8);
  const int bn = (lane & 7) + hi8;
  const int bk = lane & 8;
  const uint32_t bAddrH = smaddr(BhB + (wn + bn) * 40 + bk);
  const uint32_t bAddrL = smaddr(BlB + (wn + bn) * 40 + bk);

  auto loadTile = [&](int k0, int buf) {
#pragma unroll
    for (int u = tid; u < 512; u += 256) {
      int row = u >> 2, seg = u & 3;
      size_t ga = (size_t)(mBase + row) * 512 + k0 + seg * 8;
      int so = buf * 5120 + row * 40 + seg * 8;
      CP16(smaddr(AhB + so), Ahg + ga);
      CP16(smaddr(AlB + so), Alg + ga);
    }
    {
      int row = tid >> 2, seg = tid & 3;
      size_t ga = (size_t)(nBase + row) * 512 + k0 + seg * 8;
      int so = buf * 2560 + row * 40 + seg * 8;
      CP16(smaddr(BhB + so), Bhg + ga);
      CP16(smaddr(BlB + so), Blg + ga);
    }
    CP_COMMIT();
  };

  float acc[2][4][4];
#pragma unroll
  for (int mi = 0; mi < 2; ++mi)
#pragma unroll
    for (int j = 0; j < 4; ++j)
#pragma unroll
      for (int q = 0; q < 4; ++q) acc[mi][j][q] = 0.0f;

  loadTile(0, 0);
#pragma unroll
  for (int t = 0; t < 2; ++t) {
    if (t < 1) { loadTile(32, 1); CP_WAIT1(); }
    else CP_WAIT0();
    __syncthreads();
    const uint32_t aOff = (uint32_t)(t * 10240);
    const uint32_t bOff = (uint32_t)(t * 5120);
#pragma unroll
    for (int kk = 0; kk < 32; kk += 16) {
      uint32_t ah[2][4], al[2][4];
#pragma unroll
      for (int mi = 0; mi < 2; ++mi) {
        LDSM_X4(ah[mi][0], ah[mi][1], ah[mi][2], ah[mi][3], aAddrH + aOff + (mi * 640 + kk) * 2);
        LDSM_X4(al[mi][0], al[mi][1], al[mi][2], al[mi][3], aAddrL + aOff + (mi * 640 + kk) * 2);
      }
      uint32_t bh[4][2], bl[4][2];
#pragma unroll
      for (int p = 0; p < 2; ++p) {
        LDSM_X4(bh[2 * p][0], bh[2 * p][1], bh[2 * p + 1][0], bh[2 * p + 1][1],
                bAddrH + bOff + (p * 640 + kk) * 2);
        LDSM_X4(bl[2 * p][0], bl[2 * p][1], bl[2 * p + 1][0], bl[2 * p + 1][1],
                bAddrL + bOff + (p * 640 + kk) * 2);
      }
#pragma unroll
      for (int mi = 0; mi < 2; ++mi)
#pragma unroll
        for (int j = 0; j < 4; ++j) {
          MMA_BF16(acc[mi][j], ah[mi], bh[j]);
          MMA_BF16(acc[mi][j], ah[mi], bl[j]);
          MMA_BF16(acc[mi][j], al[mi], bh[j]);
        }
    }
    __syncthreads();
  }

#pragma unroll
  for (int mi = 0; mi < 2; ++mi) {
    int row = mBase + wm + mi * 16 + g;
    float p0 = mqb[row] ? 0.0f : 1.0e6f;
    float p1 = mqb[row + 8] ? 0.0f : 1.0e6f;
#pragma unroll
    for (int j = 0; j < 4; ++j) {
      int col = nBase + wn + j * 8 + t4 * 2;
      float c0 = mkb[col] ? 0.0f : 1.0e6f;
      float c1 = mkb[col + 1] ? 0.0f : 1.0e6f;
      *(float2*)(C + (size_t)row * Lk + col) =
          make_float2(acc[mi][j][0] - fmaxf(p0, c0), acc[mi][j][1] - fmaxf(p0, c1));
      *(float2*)(C + (size_t)(row + 8) * Lk + col) =
          make_float2(acc[mi][j][2] - fmaxf(p1, c0), acc[mi][j][3] - fmaxf(p1, c1));
    }
  }
}

// ---------------- softmax (both directions in one launch) ----------------
template <int LK>
__device__ __forceinline__ void softmax_impl(
    float* __restrict__ S, const unsigned char* __restrict__ mq,
    float* __restrict__ alphaOut, int Lq, int l, int b, float* sbuf) {
  const int tid = threadIdx.x, w = tid >> 5, lane = tid & 31;
  const size_t abase = ((size_t)b * Lq + l) * (size_t)(LK * 8);

  if (!mq[b * Lq + l]) {
    for (int idx = tid; idx < LK * 8; idx += 256) alphaOut[abase + idx] = 0.0f;
#pragma unroll
    for (int h = 0; h < 8; ++h) {
      float* srow = S + ((size_t)(b * 8 + h) * Lq + l) * LK;
      for (int k = tid; k < LK; k += 256) srow[k] = 0.0f;
    }
    return;
  }

  float* srow = S + ((size_t)(b * 8 + w) * Lq + l) * LK;
  const int nit = LK / 32;
  float v[LK / 32];
  float mx = -3.0e38f;
#pragma unroll
  for (int i = 0; i < nit; ++i) { v[i] = srow[lane + 32 * i]; mx = fmaxf(mx, v[i]); }
#pragma unroll
  for (int o = 16; o > 0; o >>= 1) mx = fmaxf(mx, __shfl_xor_sync(0xffffffffu, mx, o));
  float sum = 0.0f;
#pragma unroll
  for (int i = 0; i < nit; ++i) { float e = __expf(v[i] - mx); v[i] = e; sum += e; }
#pragma unroll
  for (int o = 16; o > 0; o >>= 1) sum += __shfl_xor_sync(0xffffffffu, sum, o);
  float inv = 1.0f / sum;
  u16* arow = (u16*)srow;
#pragma unroll
  for (int i = 0; i < nit; ++i) {
    float a = v[i] * inv;
    sbuf[w * 513 + lane + 32 * i] = a;
    u16 hb = bf16bits(a);
    arow[lane + 32 * i] = hb;
    arow[LK + lane + 32 * i] = bf16bits(a - bf16val(hb));
  }
  __syncthreads();
#pragma unroll 4
  for (int idx = tid; idx < LK * 8; idx += 256) {
    int k = idx >> 3, h = idx & 7;
    alphaOut[abase + idx] = sbuf[h * 513 + k];
  }
}

// grid 24576: [0,16384) dir1 (LK=256), [16384,24576) dir2 (LK=512)
__global__ __launch_bounds__(256) void softmax_both(
    float* __restrict__ sc, const unsigned char* __restrict__ mg,
    float* __restrict__ out) {
  __shared__ float sbuf[8 * 513];
  const int bid = blockIdx.x;
  if (bid < 16384) {
    int l = bid & 511, b = bid >> 9;
    softmax_impl<256>(sc, mg, out + 12607488u, 512, l, b, sbuf);
  } else {
    int r = bid - 16384;
    int l = r & 255, b = r >> 8;
    softmax_impl<512>(sc + 85458944, mg + 16384, out + 46161920u, 256, l, b, sbuf);
  }
}

// ====== bf16x3 AV (cp.async double-buffered, BOTH directions merged) ======
#define AV_SMEM 59392
__global__ __launch_bounds__(256) void gemm_av_mma(
    float* __restrict__ sc, float* __restrict__ out) {
  extern __shared__ __align__(16) u16 dyn[];
  u16* AhB = dyn;
  u16* AlB = dyn + 10240;
  u16* BhB = dyn + 20480;
  u16* BlB = dyn + 25088;

  const int bid = blockIdx.x;
  int Lq, Lk, x, z;
  const float* Sd;
  const u16 *Vh, *Vl;
  float* OutD;
  if (bid < 1024) {
    Lq = 512; Lk = 256;
    x = bid & 3; z = bid >> 2;
    Sd = sc;
    Vh = (const u16*)(sc + 67108864); Vl = (const u16*)(sc + 69206016);
    OutD = out;
  } else {
    int rem = bid - 1024;
    Lq = 256; Lk = 512;
    x = rem & 1; z = rem >> 1;
    Sd = sc + 85458944;
    Vh = (const u16*)(sc + 50331648); Vl = (const u16*)(sc + 54525952);
    OutD = out + 8388608;
  }
  const int tid = threadIdx.x;
  const int w = tid >> 5, lane = tid & 31;
  const int g = lane >> 2, t4 = lane & 3;
  const int wm = (w >> 1) * 32, wn = (w & 1) * 32;
  const int mBase = x * 128;
  const int b = z >> 3, h = z & 7;
  const u16* Abase = (const u16*)(Sd + (size_t)z * Lq * Lk);
  const size_t vbase = (size_t)b * Lk * 512 + h * 64;
  float* C = OutD + (size_t)b * Lq * 512 + h * 64;

  const int lane15 = lane & 15;
  const int hi8 = (lane >> 4) << 3;
  const uint32_t aAddrH = smaddr(AhB + (wm + lane15) * 40 + hi8);
  const uint32_t aAddrL = smaddr(AlB + (wm + lane15) * 40 + hi8);
  const int bkOff = (lane & 7) + (lane & 8);
  const uint32_t bAddrH = smaddr(BhB + bkOff * 72 + wn + hi8);
  const uint32_t bAddrL = smaddr(BlB + bkOff * 72 + wn + hi8);

  auto loadTile = [&](int k0, int buf) {
#pragma unroll
    for (int u = tid; u < 512; u += 256) {
      int row = u >> 2, seg = u & 3;
      const u16* ar = Abase + (size_t)(mBase + row) * 2 * Lk + k0 + seg * 8;
      int so = buf * 5120 + row * 40 + seg * 8;
      CP16(smaddr(AhB + so), ar);
      CP16(smaddr(AlB + so), ar + Lk);
    }
    {
      int row = tid >> 3, seg = tid & 7;
      size_t ga = vbase + (size_t)(k0 + row) * 512 + seg * 8;
      int so = buf * 2304 + row * 72 + seg * 8;
      CP16(smaddr(BhB + so), Vh + ga);
      CP16(smaddr(BlB + so), Vl + ga);
    }
    CP_COMMIT();
  };

  float acc[2][4][4];
#pragma unroll
  for (int mi = 0; mi < 2; ++mi)
#pragma unroll
    for (int j = 0; j < 4; ++j)
#pragma unroll
      for (int q = 0; q < 4; ++q) acc[mi][j][q] = 0.0f;

  const int T = Lk / 32;
  loadTile(0, 0);
  for (int t = 0; t < T; ++t) {
    if (t < T - 1) { loadTile((t + 1) * 32, (t + 1) & 1); CP_WAIT1(); }
    else CP_WAIT0();
    __syncthreads();
    const uint32_t aOff = (uint32_t)((t & 1) * 10240);
    const uint32_t bOff = (uint32_t)((t & 1) * 4608);
#pragma unroll
    for (int kk = 0; kk < 32; kk += 16) {
      uint32_t ah[2][4], al[2][4];
#pragma unroll
      for (int mi = 0; mi < 2; ++mi) {
        LDSM_X4(ah[mi][0], ah[mi][1], ah[mi][2], ah[mi][3], aAddrH + aOff + (mi * 640 + kk) * 2);
        LDSM_X4(al[mi][0], al[mi][1], al[mi][2], al[mi][3], aAddrL + aOff + (mi * 640 + kk) * 2);
      }
      uint32_t bh[4][2], bl[4][2];
#pragma unroll
      for (int p = 0; p < 2; ++p) {
        LDSM_X4_T(bh[2 * p][0], bh[2 * p][1], bh[2 * p + 1][0], bh[2 * p + 1][1],
                  bAddrH + bOff + (kk * 72 + p * 16) * 2);
        LDSM_X4_T(bl[2 * p][0], bl[2 * p][1], bl[2 * p + 1][0], bl[2 * p + 1][1],
                  bAddrL + bOff + (kk * 72 + p * 16) * 2);
      }
#pragma unroll
      for (int mi = 0; mi < 2; ++mi)
#pragma unroll
        for (int j = 0; j < 4; ++j) {
          MMA_BF16(acc[mi][j], ah[mi], bh[j]);
          MMA_BF16(acc[mi][j], ah[mi], bl[j]);
          MMA_BF16(acc[mi][j], al[mi], bh[j]);
        }
    }
    __syncthreads();
  }

#pragma unroll
  for (int mi = 0; mi < 2; ++mi) {
    int row = mBase + wm + mi * 16 + g;
#pragma unroll
    for (int j = 0; j < 4; ++j) {
      int col = wn + j * 8 + t4 * 2;
      *(float2*)(C + (size_t)row * 512 + col) = make_float2(acc[mi][j][0], acc[mi][j][1]);
      *(float2*)(C + (size_t)(row + 8) * 512 + col) = make_float2(acc[mi][j][2], acc[mi][j][3]);
    }
  }
}

// ---------------- launch ----------------
extern "C" void kernel_launch(void* const* d_in, const int* in_sizes, int n_in,
                              void* d_out, int out_size) {
  const float* protein = (const float*)d_in[0];
  const float* drug    = (const float*)d_in[1];
  const void*  mpraw   = d_in[2];
  const void*  mdraw   = d_in[3];
  const float* W[6] = {(const float*)d_in[4], (const float*)d_in[5], (const float*)d_in[6],
                       (const float*)d_in[7], (const float*)d_in[8], (const float*)d_in[9]};
  float* out = (float*)d_out;

  float* sc = nullptr;
  cudaGetSymbolAddress((void**)&sc, g_scratch);
  unsigned char* mg = nullptr;
  cudaGetSymbolAddress((void**)&mg, g_masks);

  u16* QPh = (u16*)(sc + 33554432);
  u16* PGH = (u16*)(sc + 71303168); u16* PGL = (u16*)(sc + 75497472);
  u16* DRH = (u16*)(sc + 79691776); u16* DRL = (u16*)(sc + 81788928);
  u16* WHb = (u16*)(sc + 83886080); u16* WLb = (u16*)(sc + 84672512);

  const size_t OFF_MP = 12582912;
  const size_t OFF_MD = 12599296;

  static int attr_done = 0;
  if (!attr_done) {
    cudaFuncSetAttribute(gemm_proj_mma, cudaFuncAttributeMaxDynamicSharedMemorySize, PROJ_SMEM);
    cudaFuncSetAttribute(gemm_logits_mma, cudaFuncAttributeMaxDynamicSharedMemorySize, LOGITS_SMEM);
    cudaFuncSetAttribute(gemm_av_mma, cudaFuncAttributeMaxDynamicSharedMemorySize, AV_SMEM);
    attr_done = 1;
  }

  detect_kernel<<<1, 1>>>((const unsigned char*)mpraw);
  prep_all<<<3552, 256>>>(protein, drug,
                          (const float4*)W[0], (const float4*)W[1], (const float4*)W[2],
                          (const float4*)W[3], (const float4*)W[4], (const float4*)W[5],
                          mpraw, mdraw,
                          (uint2*)PGH, (uint2*)PGL, (uint2*)DRH, (uint2*)DRL,
                          (uint2*)WHb, (uint2*)WLb,
                          out + OFF_MP, out + OFF_MD);

  gemm_proj_mma<<<4608, 256, PROJ_SMEM>>>(PGH, PGL, DRH, DRL, WHb, WLb, QPh);
  gemm_logits_mma<<<8192, 256, LOGITS_SMEM>>>(sc, mg);
  softmax_both<<<24576, 256>>>(sc, mg, out);
  gemm_av_mma<<<1536, 256, AV_SMEM>>>(sc, out);

  (void)in_sizes; (void)n_in; (void)out_size;
}

// round 16
// speedup vs baseline: 1.1342x; 1.0202x over previous
#include <cuda_runtime.h>
#include <cuda_bf16.h>
#include <cstdint>

#define NB    32
#define LP    2048
#define LDRG  256
#define DD    512
#define GPNUM 512

typedef unsigned short u16;

// ======================= scratch (floats) =======================
// S1 @0 (33554432), Q/K/V bf16 @33554432.., PG/DR/W @71303168.., S2 @85458944
__device__ float g_scratch[119013376];
__device__ unsigned char g_masks[24576];
__device__ int g_flag;

__device__ __forceinline__ u16 bf16bits(float x) {
  __nv_bfloat16 h = __float2bfloat16_rn(x);
  return *reinterpret_cast<u16*>(&h);
}
__device__ __forceinline__ float bf16val(u16 b) {
  __nv_bfloat16 h = *reinterpret_cast<__nv_bfloat16*>(&b);
  return __bfloat162float(h);
}
__device__ __forceinline__ void split2(float v0, float v1, uint32_t& hi, uint32_t& lo) {
  u16 h0 = bf16bits(v0), h1 = bf16bits(v1);
  u16 l0 = bf16bits(v0 - bf16val(h0)), l1 = bf16bits(v1 - bf16val(h1));
  hi = (uint32_t)h0 | ((uint32_t)h1 << 16);
  lo = (uint32_t)l0 | ((uint32_t)l1 << 16);
}
__device__ __forceinline__ uint32_t smaddr(const void* p) {
  return (uint32_t)__cvta_generic_to_shared(p);
}

#define CP16(s, g) \
  asm volatile("cp.async.cg.shared.global [%0], [%1], 16;" :: "r"(s), "l"(g))
#define CP_COMMIT() asm volatile("cp.async.commit_group;" ::: "memory")
#define CP_WAIT0() asm volatile("cp.async.wait_group 0;" ::: "memory")
#define CP_WAIT1() asm volatile("cp.async.wait_group 1;" ::: "memory")

// ======================= masks / detect =======================
__device__ __forceinline__ bool read_mask(const void* p, int i, int f) {
  if (f == 0) return ((const unsigned char*)p)[i] != 0;
  if (f == 1) return ((const int*)p)[i] != 0;
  return ((const float*)p)[i] != 0.0f;
}
__global__ void detect_kernel(const unsigned char* __restrict__ p) {
  int big = 0, off = 0;
  for (int i = 0; i < 1024; ++i) {
    unsigned char c = p[i];
    big |= (c > 1) ? 1 : 0;
    off |= (c != 0 && (i & 3) != 0) ? 1 : 0;
  }
  g_flag = big ? 2 : (off ? 0 : 1);
}

// ====== merged pre-processing: group + drug cvt + weight cvt + masks ======
__global__ void prep_all(const float* __restrict__ P, const float* __restrict__ Dr,
                         const float4* w0, const float4* w1, const float4* w2,
                         const float4* w3, const float4* w4, const float4* w5,
                         const void* __restrict__ mpraw, const void* __restrict__ mdraw,
                         uint2* __restrict__ PGHp, uint2* __restrict__ PGLp,
                         uint2* __restrict__ DRHp, uint2* __restrict__ DRLp,
                         uint2* __restrict__ WHp, uint2* __restrict__ WLp,
                         float* __restrict__ outMP, float* __restrict__ outMD) {
  const int bid = blockIdx.x;
  const int tid = threadIdx.x;
  if (bid < 2048) {
#pragma unroll
    for (int it = 0; it < 4; ++it) {
      int idx = bid * 1024 + it * 256 + tid;
      int d4 = idx & 127;
      int g = (idx >> 7) & 511;
      int b = idx >> 16;
      const float* p = P + ((size_t)b * LP + (size_t)g * 4) * DD + d4 * 4;
      float4 x0 = *(const float4*)p;
      float4 x1 = *(const float4*)(p + 512);
      float4 x2 = *(const float4*)(p + 1024);
      float4 x3 = *(const float4*)(p + 1536);
      float v0 = 0.25f * (x0.x + x1.x + x2.x + x3.x);
      float v1 = 0.25f * (x0.y + x1.y + x2.y + x3.y);
      float v2 = 0.25f * (x0.z + x1.z + x2.z + x3.z);
      float v3 = 0.25f * (x0.w + x1.w + x2.w + x3.w);
      uint32_t h01, l01, h23, l23;
      split2(v0, v1, h01, l01);
      split2(v2, v3, h23, l23);
      PGHp[idx] = make_uint2(h01, h23);
      PGLp[idx] = make_uint2(l01, l23);
    }
  } else if (bid < 3072) {
    int b2 = bid - 2048;
    const float4* X = (const float4*)Dr;
#pragma unroll
    for (int it = 0; it < 4; ++it) {
      int i = b2 * 1024 + it * 256 + tid;
      float4 x = X[i];
      uint32_t h01, l01, h23, l23;
      split2(x.x, x.y, h01, l01);
      split2(x.z, x.w, h23, l23);
      DRHp[i] = make_uint2(h01, h23);
      DRLp[i] = make_uint2(l01, l23);
    }
  } else if (bid < 3456) {
    int b3 = bid - 3072;
    int wi = b3 >> 6, xb = b3 & 63;
    const float4* X = (wi == 0) ? w0 : (wi == 1) ? w1 : (wi == 2) ? w2
                     : (wi == 3) ? w3 : (wi == 4) ? w4 : w5;
#pragma unroll
    for (int it = 0; it < 4; ++it) {
      int i = xb * 1024 + it * 256 + tid;
      float4 x = X[i];
      uint32_t h01, l01, h23, l23;
      split2(x.x, x.y, h01, l01);
      split2(x.z, x.w, h23, l23);
      size_t o = (size_t)wi * 65536 + i;
      WHp[o] = make_uint2(h01, h23);
      WLp[o] = make_uint2(l01, l23);
    }
  } else {
    int f = g_flag;
    int idx = (bid - 3456) * 256 + tid;
    if (idx < NB * GPNUM) {
      int b = idx / GPNUM, g = idx % GPNUM;
      int base = b * LP + g * 4;
      bool any = false;
#pragma unroll
      for (int r = 0; r < 4; ++r) any = any || read_mask(mpraw, base + r, f);
      g_masks[idx] = any ? 1 : 0;
      outMP[idx] = any ? 1.0f : 0.0f;
    } else {
      int j = idx - NB * GPNUM;
      if (j < NB * LDRG) {
        bool v = read_mask(mdraw, j, f);
        g_masks[16384 + j] = v ? 1 : 0;
        outMD[j] = v ? 1.0f : 0.0f;
      }
    }
  }
}

// ======================= MMA / ldmatrix macros =======================
#define MMA_BF16(c, a, b)                                                      \
  asm volatile("mma.sync.aligned.m16n8k16.row.col.f32.bf16.bf16.f32 "          \
               "{%0,%1,%2,%3}, {%4,%5,%6,%7}, {%8,%9}, {%0,%1,%2,%3};"         \
               : "+f"((c)[0]), "+f"((c)[1]), "+f"((c)[2]), "+f"((c)[3])        \
               : "r"((a)[0]), "r"((a)[1]), "r"((a)[2]), "r"((a)[3]),           \
                 "r"((b)[0]), "r"((b)[1]))

#define LDSM_X4(r0, r1, r2, r3, a)                                             \
  asm volatile("ldmatrix.sync.aligned.m8n8.x4.shared.b16 {%0,%1,%2,%3}, [%4];" \
               : "=r"(r0), "=r"(r1), "=r"(r2), "=r"(r3) : "r"(a))

#define LDSM_X4_T(r0, r1, r2, r3, a)                                           \
  asm volatile("ldmatrix.sync.aligned.m8n8.x4.trans.shared.b16 {%0,%1,%2,%3}, [%4];" \
               : "=r"(r0), "=r"(r1), "=r"(r2), "=r"(r3) : "r"(a))

// ====== bf16x3 projection (cp.async double-buffered, ALL 6 GEMMs merged) ======
#define PROJ_SMEM 61440
__global__ __launch_bounds__(256) void gemm_proj_mma(
    const u16* __restrict__ PGHp, const u16* __restrict__ PGLp,
    const u16* __restrict__ DRHp, const u16* __restrict__ DRLp,
    const u16* __restrict__ WHb, const u16* __restrict__ WLb,
    u16* __restrict__ OutBase) {
  extern __shared__ __align__(16) u16 dyn[];
  u16* AhB = dyn;
  u16* AlB = dyn + 10240;
  u16* BhB = dyn + 20480;
  u16* BlB = dyn + 25600;

  const int bid = blockIdx.x;
  int wi, x, y, loGap;
  size_t outOff;
  const u16 *Ah, *Al;
  if (bid < 3072) {
    wi = bid >> 10;
    int rem = bid & 1023;
    x = rem & 127; y = rem >> 7;
    Ah = PGHp; Al = PGLp;
    outOff = (size_t)wi * 16777216u;
    loGap = 8388608;
  } else {
    int b2 = bid - 3072;
    wi = 3 + (b2 >> 9);
    int rem = b2 & 511;
    x = rem & 63; y = rem >> 6;
    Ah = DRHp; Al = DRLp;
    outOff = 50331648u + (size_t)(wi - 3) * 8388608u;
    loGap = 4194304;
  }
  const u16* Wh = WHb + (size_t)wi * 262144;
  const u16* Wl = WLb + (size_t)wi * 262144;
  u16* Ch = OutBase + outOff;
  u16* Cl = Ch + loGap;
  const int mBase = x * 128;
  const int nBase = y * 64;

  const int tid = threadIdx.x;
  const int w = tid >> 5, lane = tid & 31;
  const int g = lane >> 2, t4 = lane & 3;
  const int wm = (w >> 1) * 32, wn = (w & 1) * 32;

  const int lane15 = lane & 15;
  const int hi8 = (lane >> 4) << 3;
  const uint32_t aAddrH = smaddr(AhB + (wm + lane15) * 40 + hi8);
  const uint32_t aAddrL = smaddr(AlB + (wm + lane15) * 40 + hi8);
  const int bn = (lane & 7) + hi8;
  const int bk = lane & 8;
  const uint32_t bAddrH = smaddr(BhB + (wn + bn) * 40 + bk);
  const uint32_t bAddrL = smaddr(BlB + (wn + bn) * 40 + bk);

  auto loadTile = [&](int k0, int buf) {
#pragma unroll
    for (int u = tid; u < 512; u += 256) {
      int row = u >> 2, seg = u & 3;
      size_t ga = (size_t)(mBase + row) * 512 + k0 + seg * 8;
      int so = buf * 5120 + row * 40 + seg * 8;
      CP16(smaddr(AhB + so), Ah + ga);
      CP16(smaddr(AlB + so), Al + ga);
    }
    {
      int row = tid >> 2, seg = tid & 3;
      size_t ga = (size_t)(nBase + row) * 512 + k0 + seg * 8;
      int so = buf * 2560 + row * 40 + seg * 8;
      CP16(smaddr(BhB + so), Wh + ga);
      CP16(smaddr(BlB + so), Wl + ga);
    }
    CP_COMMIT();
  };

  float acc[2][4][4];
#pragma unroll
  for (int mi = 0; mi < 2; ++mi)
#pragma unroll
    for (int j = 0; j < 4; ++j)
#pragma unroll
      for (int q = 0; q < 4; ++q) acc[mi][j][q] = 0.0f;

  loadTile(0, 0);
  for (int t = 0; t < 16; ++t) {
    if (t < 15) { loadTile((t + 1) * 32, (t + 1) & 1); CP_WAIT1(); }
    else CP_WAIT0();
    __syncthreads();
    const uint32_t aOff = (uint32_t)((t & 1) * 10240);
    const uint32_t bOff = (uint32_t)((t & 1) * 5120);
#pragma unroll
    for (int kk = 0; kk < 32; kk += 16) {
      uint32_t ah[2][4], al[2][4];
#pragma unroll
      for (int mi = 0; mi < 2; ++mi) {
        LDSM_X4(ah[mi][0], ah[mi][1], ah[mi][2], ah[mi][3], aAddrH + aOff + (mi * 640 + kk) * 2);
        LDSM_X4(al[mi][0], al[mi][1], al[mi][2], al[mi][3], aAddrL + aOff + (mi * 640 + kk) * 2);
      }
      uint32_t bh[4][2], bl[4][2];
#pragma unroll
      for (int p = 0; p < 2; ++p) {
        LDSM_X4(bh[2 * p][0], bh[2 * p][1], bh[2 * p + 1][0], bh[2 * p + 1][1],
                bAddrH + bOff + (p * 640 + kk) * 2);
        LDSM_X4(bl[2 * p][0], bl[2 * p][1], bl[2 * p + 1][0], bl[2 * p + 1][1],
                bAddrL + bOff + (p * 640 + kk) * 2);
      }
#pragma unroll
      for (int mi = 0; mi < 2; ++mi)
#pragma unroll
        for (int j = 0; j < 4; ++j) {
          MMA_BF16(acc[mi][j], ah[mi], bh[j]);
          MMA_BF16(acc[mi][j], ah[mi], bl[j]);
          MMA_BF16(acc[mi][j], al[mi], bh[j]);
        }
    }
    __syncthreads();
  }

#pragma unroll
  for (int mi = 0; mi < 2; ++mi) {
    int row = mBase + wm + mi * 16 + g;
#pragma unroll
    for (int j = 0; j < 4; ++j) {
      int col = nBase + wn + j * 8 + t4 * 2;
      uint32_t hi, lo;
      split2(acc[mi][j][0], acc[mi][j][1], hi, lo);
      *(uint32_t*)(Ch + (size_t)row * 512 + col) = hi;
      *(uint32_t*)(Cl + (size_t)row * 512 + col) = lo;
      split2(acc[mi][j][2], acc[mi][j][3], hi, lo);
      *(uint32_t*)(Ch + (size_t)(row + 8) * 512 + col) = hi;
      *(uint32_t*)(Cl + (size_t)(row + 8) * 512 + col) = lo;
    }
  }
}

// ====== bf16x3 logits (single-buffer K=64, 4 CTA/SM, BOTH directions merged) ======
// smem (u16): Ah[128*72]=9216, Al 9216, Bh[64*72]=4608, Bl 4608 -> 27648 u16 = 55296 B
#define LOGITS_SMEM 55296
__global__ __launch_bounds__(256) void gemm_logits_mma(
    float* __restrict__ sc, const unsigned char* __restrict__ mg) {
  extern __shared__ __align__(16) u16 dyn[];
  u16* AhB = dyn;
  u16* AlB = dyn + 9216;
  u16* BhB = dyn + 18432;
  u16* BlB = dyn + 23040;

  const int bid = blockIdx.x;
  int Lq, Lk, x, y, z;
  const u16 *Qh, *Ql, *Kh, *Kl;
  float* Sd;
  const unsigned char *mqB, *mkB;
  if (bid < 4096) {
    Lq = 512; Lk = 256;
    x = bid & 3; y = (bid >> 2) & 3; z = bid >> 4;
    Qh = (const u16*)(sc + 33554432); Ql = (const u16*)(sc + 37748736);
    Kh = (const u16*)(sc + 62914560); Kl = (const u16*)(sc + 65011712);
    Sd = sc;
    mqB = mg; mkB = mg + 16384;
  } else {
    int rem = bid - 4096;
    Lq = 256; Lk = 512;
    x = rem & 1; y = (rem >> 1) & 7; z = rem >> 4;
    Qh = (const u16*)(sc + 58720256); Ql = (const u16*)(sc + 60817408);
    Kh = (const u16*)(sc + 41943040); Kl = (const u16*)(sc + 46137344);
    Sd = sc + 85458944;
    mqB = mg + 16384; mkB = mg;
  }
  const int tid = threadIdx.x;
  const int w = tid >> 5, lane = tid & 31;
  const int g = lane >> 2, t4 = lane & 3;
  const int wm = (w >> 1) * 32, wn = (w & 1) * 32;
  const int mBase = x * 128;
  const int nBase = y * 64;
  const int b = z >> 3, h = z & 7;
  const u16* Ahg = Qh + (size_t)b * Lq * 512 + h * 64;
  const u16* Alg = Ql + (size_t)b * Lq * 512 + h * 64;
  const u16* Bhg = Kh + (size_t)b * Lk * 512 + h * 64;
  const u16* Blg = Kl + (size_t)b * Lk * 512 + h * 64;
  float* C = Sd + (size_t)z * Lq * Lk;
  const unsigned char* mqb = mqB + b * Lq;
  const unsigned char* mkb = mkB + b * Lk;

  const int lane15 = lane & 15;
  const int hi8 = (lane >> 4) << 3;
  const uint32_t aAddrH = smaddr(AhB + (wm + lane15) * 72 + hi8);
  const uint32_t aAddrL = smaddr(AlB + (wm + lane15) * 72 + hi8);
  const int bn = (lane & 7) + hi8;
  const int bk = lane & 8;
  const uint32_t bAddrH = smaddr(BhB + (wn + bn) * 72 + bk);
  const uint32_t bAddrL = smaddr(BlB + (wn + bn) * 72 + bk);

  // load full K=64 in one shot: A rows 128 x 8 segs, B rows 64 x 8 segs
#pragma unroll
  for (int u = tid; u < 1024; u += 256) {
    int row = u >> 3, seg = u & 7;
    size_t ga = (size_t)(mBase + row) * 512 + seg * 8;
    int so = row * 72 + seg * 8;
    CP16(smaddr(AhB + so), Ahg + ga);
    CP16(smaddr(AlB + so), Alg + ga);
  }
#pragma unroll
  for (int u = tid; u < 512; u += 256) {
    int row = u >> 3, seg = u & 7;
    size_t ga = (size_t)(nBase + row) * 512 + seg * 8;
    int so = row * 72 + seg * 8;
    CP16(smaddr(BhB + so), Bhg + ga);
    CP16(smaddr(BlB + so), Blg + ga);
  }
  CP_COMMIT();

  float acc[2][4][4];
#pragma unroll
  for (int mi = 0; mi < 2; ++mi)
#pragma unroll
    for (int j = 0; j < 4; ++j)
#pragma unroll
      for (int q = 0; q < 4; ++q) acc[mi][j][q] = 0.0f;

  CP_WAIT0();
  __syncthreads();
#pragma unroll
  for (int kk = 0; kk < 64; kk += 16) {
    uint32_t ah[2][4], al[2][4];
#pragma unroll
    for (int mi = 0; mi < 2; ++mi) {
      LDSM_X4(ah[mi][0], ah[mi][1], ah[mi][2], ah[mi][3], aAddrH + (mi * 1152 + kk) * 2);
      LDSM_X4(al[mi][0], al[mi][1], al[mi][2], al[mi][3], aAddrL + (mi * 1152 + kk) * 2);
    }
    uint32_t bh[4][2], bl[4][2];
#pragma unroll
    for (int p = 0; p < 2; ++p) {
      LDSM_X4(bh[2 * p][0], bh[2 * p][1], bh[2 * p + 1][0], bh[2 * p + 1][1],
              bAddrH + (p * 1152 + kk) * 2);
      LDSM_X4(bl[2 * p][0], bl[2 * p][1], bl[2 * p + 1][0], bl[2 * p + 1][1],
              bAddrL + (p * 1152 + kk) * 2);
    }
#pragma unroll
    for (int mi = 0; mi < 2; ++mi)
#pragma unroll
      for (int j = 0; j < 4; ++j) {
        MMA_BF16(acc[mi][j], ah[mi], bh[j]);
        MMA_BF16(acc[mi][j], ah[mi], bl[j]);
        MMA_BF16(acc[mi][j], al[mi], bh[j]);
      }
  }

#pragma unroll
  for (int mi = 0; mi < 2; ++mi) {
    int row = mBase + wm + mi * 16 + g;
    float p0 = mqb[row] ? 0.0f : 1.0e6f;
    float p1 = mqb[row + 8] ? 0.0f : 1.0e6f;
#pragma unroll
    for (int j = 0; j < 4; ++j) {
      int col = nBase + wn + j * 8 + t4 * 2;
      float c0 = mkb[col] ? 0.0f : 1.0e6f;
      float c1 = mkb[col + 1] ? 0.0f : 1.0e6f;
      *(float2*)(C + (size_t)row * Lk + col) =
          make_float2(acc[mi][j][0] - fmaxf(p0, c0), acc[mi][j][1] - fmaxf(p0, c1));
      *(float2*)(C + (size_t)(row + 8) * Lk + col) =
          make_float2(acc[mi][j][2] - fmaxf(p1, c0), acc[mi][j][3] - fmaxf(p1, c1));
    }
  }
}

// ---------------- softmax (both directions in one launch) ----------------
template <int LK>
__device__ __forceinline__ void softmax_impl(
    float* __restrict__ S, const unsigned char* __restrict__ mq,
    float* __restrict__ alphaOut, int Lq, int l, int b, float* sbuf) {
  const int tid = threadIdx.x, w = tid >> 5, lane = tid & 31;
  const size_t abase = ((size_t)b * Lq + l) * (size_t)(LK * 8);

  if (!mq[b * Lq + l]) {
    for (int idx = tid; idx < LK * 8; idx += 256) alphaOut[abase + idx] = 0.0f;
#pragma unroll
    for (int h = 0; h < 8; ++h) {
      float* srow = S + ((size_t)(b * 8 + h) * Lq + l) * LK;
      for (int k = tid; k < LK; k += 256) srow[k] = 0.0f;
    }
    return;
  }

  float* srow = S + ((size_t)(b * 8 + w) * Lq + l) * LK;
  const int nit = LK / 32;
  float v[LK / 32];
  float mx = -3.0e38f;
#pragma unroll
  for (int i = 0; i < nit; ++i) { v[i] = srow[lane + 32 * i]; mx = fmaxf(mx, v[i]); }
#pragma unroll
  for (int o = 16; o > 0; o >>= 1) mx = fmaxf(mx, __shfl_xor_sync(0xffffffffu, mx, o));
  float sum = 0.0f;
#pragma unroll
  for (int i = 0; i < nit; ++i) { float e = __expf(v[i] - mx); v[i] = e; sum += e; }
#pragma unroll
  for (int o = 16; o > 0; o >>= 1) sum += __shfl_xor_sync(0xffffffffu, sum, o);
  float inv = 1.0f / sum;
  u16* arow = (u16*)srow;
#pragma unroll
  for (int i = 0; i < nit; ++i) {
    float a = v[i] * inv;
    sbuf[w * 513 + lane + 32 * i] = a;
    u16 hb = bf16bits(a);
    arow[lane + 32 * i] = hb;
    arow[LK + lane + 32 * i] = bf16bits(a - bf16val(hb));
  }
  __syncthreads();
#pragma unroll 4
  for (int idx = tid; idx < LK * 8; idx += 256) {
    int k = idx >> 3, h = idx & 7;
    alphaOut[abase + idx] = sbuf[h * 513 + k];
  }
}

__global__ __launch_bounds__(256) void softmax_both(
    float* __restrict__ sc, const unsigned char* __restrict__ mg,
    float* __restrict__ out) {
  __shared__ float sbuf[8 * 513];
  const int bid = blockIdx.x;
  if (bid < 16384) {
    int l = bid & 511, b = bid >> 9;
    softmax_impl<256>(sc, mg, out + 12607488u, 512, l, b, sbuf);
  } else {
    int r = bid - 16384;
    int l = r & 255, b = r >> 8;
    softmax_impl<512>(sc + 85458944, mg + 16384, out + 46161920u, 256, l, b, sbuf);
  }
}

// ====== bf16x3 AV (cp.async double-buffered, BOTH directions merged) ======
#define AV_SMEM 59392
__global__ __launch_bounds__(256) void gemm_av_mma(
    float* __restrict__ sc, float* __restrict__ out) {
  extern __shared__ __align__(16) u16 dyn[];
  u16* AhB = dyn;
  u16* AlB = dyn + 10240;
  u16* BhB = dyn + 20480;
  u16* BlB = dyn + 25088;

  const int bid = blockIdx.x;
  int Lq, Lk, x, z;
  const float* Sd;
  const u16 *Vh, *Vl;
  float* OutD;
  if (bid < 1024) {
    Lq = 512; Lk = 256;
    x = bid & 3; z = bid >> 2;
    Sd = sc;
    Vh = (const u16*)(sc + 67108864); Vl = (const u16*)(sc + 69206016);
    OutD = out;
  } else {
    int rem = bid - 1024;
    Lq = 256; Lk = 512;
    x = rem & 1; z = rem >> 1;
    Sd = sc + 85458944;
    Vh = (const u16*)(sc + 50331648); Vl = (const u16*)(sc + 54525952);
    OutD = out + 8388608;
  }
  const int tid = threadIdx.x;
  const int w = tid >> 5, lane = tid & 31;
  const int g = lane >> 2, t4 = lane & 3;
  const int wm = (w >> 1) * 32, wn = (w & 1) * 32;
  const int mBase = x * 128;
  const int b = z >> 3, h = z & 7;
  const u16* Abase = (const u16*)(Sd + (size_t)z * Lq * Lk);
  const size_t vbase = (size_t)b * Lk * 512 + h * 64;
  float* C = OutD + (size_t)b * Lq * 512 + h * 64;

  const int lane15 = lane & 15;
  const int hi8 = (lane >> 4) << 3;
  const uint32_t aAddrH = smaddr(AhB + (wm + lane15) * 40 + hi8);
  const uint32_t aAddrL = smaddr(AlB + (wm + lane15) * 40 + hi8);
  const int bkOff = (lane & 7) + (lane & 8);
  const uint32_t bAddrH = smaddr(BhB + bkOff * 72 + wn + hi8);
  const uint32_t bAddrL = smaddr(BlB + bkOff * 72 + wn + hi8);

  auto loadTile = [&](int k0, int buf) {
#pragma unroll
    for (int u = tid; u < 512; u += 256) {
      int row = u >> 2, seg = u & 3;
      const u16* ar = Abase + (size_t)(mBase + row) * 2 * Lk + k0 + seg * 8;
      int so = buf * 5120 + row * 40 + seg * 8;
      CP16(smaddr(AhB + so), ar);
      CP16(smaddr(AlB + so), ar + Lk);
    }
    {
      int row = tid >> 3, seg = tid & 7;
      size_t ga = vbase + (size_t)(k0 + row) * 512 + seg * 8;
      int so = buf * 2304 + row * 72 + seg * 8;
      CP16(smaddr(BhB + so), Vh + ga);
      CP16(smaddr(BlB + so), Vl + ga);
    }
    CP_COMMIT();
  };

  float acc[2][4][4];
#pragma unroll
  for (int mi = 0; mi < 2; ++mi)
#pragma unroll
    for (int j = 0; j < 4; ++j)
#pragma unroll
      for (int q = 0; q < 4; ++q) acc[mi][j][q] = 0.0f;

  const int T = Lk / 32;
  loadTile(0, 0);
  for (int t = 0; t < T; ++t) {
    if (t < T - 1) { loadTile((t + 1) * 32, (t + 1) & 1); CP_WAIT1(); }
    else CP_WAIT0();
    __syncthreads();
    const uint32_t aOff = (uint32_t)((t & 1) * 10240);
    const uint32_t bOff = (uint32_t)((t & 1) * 4608);
#pragma unroll
    for (int kk = 0; kk < 32; kk += 16) {
      uint32_t ah[2][4], al[2][4];
#pragma unroll
      for (int mi = 0; mi < 2; ++mi) {
        LDSM_X4(ah[mi][0], ah[mi][1], ah[mi][2], ah[mi][3], aAddrH + aOff + (mi * 640 + kk) * 2);
        LDSM_X4(al[mi][0], al[mi][1], al[mi][2], al[mi][3], aAddrL + aOff + (mi * 640 + kk) * 2);
      }
      uint32_t bh[4][2], bl[4][2];
#pragma unroll
      for (int p = 0; p < 2; ++p) {
        LDSM_X4_T(bh[2 * p][0], bh[2 * p][1], bh[2 * p + 1][0], bh[2 * p + 1][1],
                  bAddrH + bOff + (kk * 72 + p * 16) * 2);
        LDSM_X4_T(bl[2 * p][0], bl[2 * p][1], bl[2 * p + 1][0], bl[2 * p + 1][1],
                  bAddrL + bOff + (kk * 72 + p * 16) * 2);
      }
#pragma unroll
      for (int mi = 0; mi < 2; ++mi)
#pragma unroll
        for (int j = 0; j < 4; ++j) {
          MMA_BF16(acc[mi][j], ah[mi], bh[j]);
          MMA_BF16(acc[mi][j], ah[mi], bl[j]);
          MMA_BF16(acc[mi][j], al[mi], bh[j]);
        }
    }
    __syncthreads();
  }

#pragma unroll
  for (int mi = 0; mi < 2; ++mi) {
    int row = mBase + wm + mi * 16 + g;
#pragma unroll
    for (int j = 0; j < 4; ++j) {
      int col = wn + j * 8 + t4 * 2;
      *(float2*)(C + (size_t)row * 512 + col) = make_float2(acc[mi][j][0], acc[mi][j][1]);
      *(float2*)(C + (size_t)(row + 8) * 512 + col) = make_float2(acc[mi][j][2], acc[mi][j][3]);
    }
  }
}

// ---------------- launch ----------------
extern "C" void kernel_launch(void* const* d_in, const int* in_sizes, int n_in,
                              void* d_out, int out_size) {
  const float* protein = (const float*)d_in[0];
  const float* drug    = (const float*)d_in[1];
  const void*  mpraw   = d_in[2];
  const void*  mdraw   = d_in[3];
  const float* W[6] = {(const float*)d_in[4], (const float*)d_in[5], (const float*)d_in[6],
                       (const float*)d_in[7], (const float*)d_in[8], (const float*)d_in[9]};
  float* out = (float*)d_out;

  float* sc = nullptr;
  cudaGetSymbolAddress((void**)&sc, g_scratch);
  unsigned char* mg = nullptr;
  cudaGetSymbolAddress((void**)&mg, g_masks);

  u16* QPh = (u16*)(sc + 33554432);
  u16* PGH = (u16*)(sc + 71303168); u16* PGL = (u16*)(sc + 75497472);
  u16* DRH = (u16*)(sc + 79691776); u16* DRL = (u16*)(sc + 81788928);
  u16* WHb = (u16*)(sc + 83886080); u16* WLb = (u16*)(sc + 84672512);

  const size_t OFF_MP = 12582912;
  const size_t OFF_MD = 12599296;

  static int attr_done = 0;
  if (!attr_done) {
    cudaFuncSetAttribute(gemm_proj_mma, cudaFuncAttributeMaxDynamicSharedMemorySize, PROJ_SMEM);
    cudaFuncSetAttribute(gemm_logits_mma, cudaFuncAttributeMaxDynamicSharedMemorySize, LOGITS_SMEM);
    cudaFuncSetAttribute(gemm_av_mma, cudaFuncAttributeMaxDynamicSharedMemorySize, AV_SMEM);
    attr_done = 1;
  }

  detect_kernel<<<1, 1>>>((const unsigned char*)mpraw);
  prep_all<<<3552, 256>>>(protein, drug,
                          (const float4*)W[0], (const float4*)W[1], (const float4*)W[2],
                          (const float4*)W[3], (const float4*)W[4], (const float4*)W[5],
                          mpraw, mdraw,
                          (uint2*)PGH, (uint2*)PGL, (uint2*)DRH, (uint2*)DRL,
                          (uint2*)WHb, (uint2*)WLb,
                          out + OFF_MP, out + OFF_MD);

  gemm_proj_mma<<<4608, 256, PROJ_SMEM>>>(PGH, PGL, DRH, DRL, WHb, WLb, QPh);
  gemm_logits_mma<<<8192, 256, LOGITS_SMEM>>>(sc, mg);
  softmax_both<<<24576, 256>>>(sc, mg, out);
  gemm_av_mma<<<1536, 256, AV_SMEM>>>(sc, out);

  (void)in_sizes; (void)n_in; (void)out_size;
}

// round 17
// speedup vs baseline: 1.1629x; 1.0253x over previous
#include <cuda_runtime.h>
#include <cuda_bf16.h>
#include <cstdint>

#define NB    32
#define LP    2048
#define LDRG  256
#define DD    512
#define GPNUM 512

typedef unsigned short u16;

// ======================= scratch (floats) =======================
// S1 @0 (33554432), Q/K/V bf16 @33554432.., PG/DR/W @71303168.., S2 @85458944
__device__ float g_scratch[119013376];
__device__ unsigned char g_masks[24576];

__device__ __forceinline__ u16 bf16bits(float x) {
  __nv_bfloat16 h = __float2bfloat16_rn(x);
  return *reinterpret_cast<u16*>(&h);
}
__device__ __forceinline__ float bf16val(u16 b) {
  __nv_bfloat16 h = *reinterpret_cast<__nv_bfloat16*>(&b);
  return __bfloat162float(h);
}
__device__ __forceinline__ void split2(float v0, float v1, uint32_t& hi, uint32_t& lo) {
  u16 h0 = bf16bits(v0), h1 = bf16bits(v1);
  u16 l0 = bf16bits(v0 - bf16val(h0)), l1 = bf16bits(v1 - bf16val(h1));
  hi = (uint32_t)h0 | ((uint32_t)h1 << 16);
  lo = (uint32_t)l0 | ((uint32_t)l1 << 16);
}
__device__ __forceinline__ uint32_t smaddr(const void* p) {
  return (uint32_t)__cvta_generic_to_shared(p);
}

#define CP16(s, g) \
  asm volatile("cp.async.cg.shared.global [%0], [%1], 16;" :: "r"(s), "l"(g))
#define CP_COMMIT() asm volatile("cp.async.commit_group;" ::: "memory")
#define CP_WAIT0() asm volatile("cp.async.wait_group 0;" ::: "memory")
#define CP_WAIT1() asm volatile("cp.async.wait_group 1;" ::: "memory")

__device__ __forceinline__ bool read_mask(const void* p, int i, int f) {
  if (f == 0) return ((const unsigned char*)p)[i] != 0;
  if (f == 1) return ((const int*)p)[i] != 0;
  return ((const float*)p)[i] != 0.0f;
}

// ====== merged pre-processing: group + drug cvt + weight cvt + masks(+detect) ======
__global__ void prep_all(const float* __restrict__ P, const float* __restrict__ Dr,
                         const float4* w0, const float4* w1, const float4* w2,
                         const float4* w3, const float4* w4, const float4* w5,
                         const void* __restrict__ mpraw, const void* __restrict__ mdraw,
                         uint2* __restrict__ PGHp, uint2* __restrict__ PGLp,
                         uint2* __restrict__ DRHp, uint2* __restrict__ DRLp,
                         uint2* __restrict__ WHp, uint2* __restrict__ WLp,
                         float* __restrict__ outMP, float* __restrict__ outMD) {
  const int bid = blockIdx.x;
  const int tid = threadIdx.x;
  if (bid < 2048) {
#pragma unroll
    for (int it = 0; it < 4; ++it) {
      int idx = bid * 1024 + it * 256 + tid;
      int d4 = idx & 127;
      int g = (idx >> 7) & 511;
      int b = idx >> 16;
      const float* p = P + ((size_t)b * LP + (size_t)g * 4) * DD + d4 * 4;
      float4 x0 = *(const float4*)p;
      float4 x1 = *(const float4*)(p + 512);
      float4 x2 = *(const float4*)(p + 1024);
      float4 x3 = *(const float4*)(p + 1536);
      float v0 = 0.25f * (x0.x + x1.x + x2.x + x3.x);
      float v1 = 0.25f * (x0.y + x1.y + x2.y + x3.y);
      float v2 = 0.25f * (x0.z + x1.z + x2.z + x3.z);
      float v3 = 0.25f * (x0.w + x1.w + x2.w + x3.w);
      uint32_t h01, l01, h23, l23;
      split2(v0, v1, h01, l01);
      split2(v2, v3, h23, l23);
      PGHp[idx] = make_uint2(h01, h23);
      PGLp[idx] = make_uint2(l01, l23);
    }
  } else if (bid < 3072) {
    int b2 = bid - 2048;
    const float4* X = (const float4*)Dr;
#pragma unroll
    for (int it = 0; it < 4; ++it) {
      int i = b2 * 1024 + it * 256 + tid;
      float4 x = X[i];
      uint32_t h01, l01, h23, l23;
      split2(x.x, x.y, h01, l01);
      split2(x.z, x.w, h23, l23);
      DRHp[i] = make_uint2(h01, h23);
      DRLp[i] = make_uint2(l01, l23);
    }
  } else if (bid < 3456) {
    int b3 = bid - 3072;
    int wi = b3 >> 6, xb = b3 & 63;
    const float4* X = (wi == 0) ? w0 : (wi == 1) ? w1 : (wi == 2) ? w2
                     : (wi == 3) ? w3 : (wi == 4) ? w4 : w5;
#pragma unroll
    for (int it = 0; it < 4; ++it) {
      int i = xb * 1024 + it * 256 + tid;
      float4 x = X[i];
      uint32_t h01, l01, h23, l23;
      split2(x.x, x.y, h01, l01);
      split2(x.z, x.w, h23, l23);
      size_t o = (size_t)wi * 65536 + i;
      WHp[o] = make_uint2(h01, h23);
      WLp[o] = make_uint2(l01, l23);
    }
  } else {
    // per-block dtype detection (redundant but parallel), then mask conversion
    __shared__ int s_big, s_off;
    if (tid == 0) { s_big = 0; s_off = 0; }
    __syncthreads();
    {
      const unsigned char* pp = (const unsigned char*)mpraw;
      int big = 0, off = 0;
#pragma unroll
      for (int r = 0; r < 4; ++r) {
        unsigned char c = pp[tid * 4 + r];
        big |= (c > 1) ? 1 : 0;
        off |= (c != 0 && r != 0) ? 1 : 0;
      }
      if (big) atomicOr(&s_big, 1);
      if (off) atomicOr(&s_off, 1);
    }
    __syncthreads();
    int f = s_big ? 2 : (s_off ? 0 : 1);
    int idx = (bid - 3456) * 256 + tid;
    if (idx < NB * GPNUM) {
      int b = idx / GPNUM, g = idx % GPNUM;
      int base = b * LP + g * 4;
      bool any = false;
#pragma unroll
      for (int r = 0; r < 4; ++r) any = any || read_mask(mpraw, base + r, f);
      g_masks[idx] = any ? 1 : 0;
      outMP[idx] = any ? 1.0f : 0.0f;
    } else {
      int j = idx - NB * GPNUM;
      if (j < NB * LDRG) {
        bool v = read_mask(mdraw, j, f);
        g_masks[16384 + j] = v ? 1 : 0;
        outMD[j] = v ? 1.0f : 0.0f;
      }
    }
  }
}

// ======================= MMA / ldmatrix macros =======================
#define MMA_BF16(c, a, b)                                                      \
  asm volatile("mma.sync.aligned.m16n8k16.row.col.f32.bf16.bf16.f32 "          \
               "{%0,%1,%2,%3}, {%4,%5,%6,%7}, {%8,%9}, {%0,%1,%2,%3};"         \
               : "+f"((c)[0]), "+f"((c)[1]), "+f"((c)[2]), "+f"((c)[3])        \
               : "r"((a)[0]), "r"((a)[1]), "r"((a)[2]), "r"((a)[3]),           \
                 "r"((b)[0]), "r"((b)[1]))

#define LDSM_X4(r0, r1, r2, r3, a)                                             \
  asm volatile("ldmatrix.sync.aligned.m8n8.x4.shared.b16 {%0,%1,%2,%3}, [%4];" \
               : "=r"(r0), "=r"(r1), "=r"(r2), "=r"(r3) : "r"(a))

#define LDSM_X4_T(r0, r1, r2, r3, a)                                           \
  asm volatile("ldmatrix.sync.aligned.m8n8.x4.trans.shared.b16 {%0,%1,%2,%3}, [%4];" \
               : "=r"(r0), "=r"(r1), "=r"(r2), "=r"(r3) : "r"(a))

// ====== bf16x3 projection (cp.async double-buffered, ALL 6 GEMMs merged) ======
#define PROJ_SMEM 61440
__global__ __launch_bounds__(256) void gemm_proj_mma(
    const u16* __restrict__ PGHp, const u16* __restrict__ PGLp,
    const u16* __restrict__ DRHp, const u16* __restrict__ DRLp,
    const u16* __restrict__ WHb, const u16* __restrict__ WLb,
    u16* __restrict__ OutBase) {
  extern __shared__ __align__(16) u16 dyn[];
  u16* AhB = dyn;
  u16* AlB = dyn + 10240;
  u16* BhB = dyn + 20480;
  u16* BlB = dyn + 25600;

  const int bid = blockIdx.x;
  int wi, x, y, loGap;
  size_t outOff;
  const u16 *Ah, *Al;
  if (bid < 3072) {
    wi = bid >> 10;
    int rem = bid & 1023;
    x = rem & 127; y = rem >> 7;
    Ah = PGHp; Al = PGLp;
    outOff = (size_t)wi * 16777216u;
    loGap = 8388608;
  } else {
    int b2 = bid - 3072;
    wi = 3 + (b2 >> 9);
    int rem = b2 & 511;
    x = rem & 63; y = rem >> 6;
    Ah = DRHp; Al = DRLp;
    outOff = 50331648u + (size_t)(wi - 3) * 8388608u;
    loGap = 4194304;
  }
  const u16* Wh = WHb + (size_t)wi * 262144;
  const u16* Wl = WLb + (size_t)wi * 262144;
  u16* Ch = OutBase + outOff;
  u16* Cl = Ch + loGap;
  const int mBase = x * 128;
  const int nBase = y * 64;

  const int tid = threadIdx.x;
  const int w = tid >> 5, lane = tid & 31;
  const int g = lane >> 2, t4 = lane & 3;
  const int wm = (w >> 1) * 32, wn = (w & 1) * 32;

  const int lane15 = lane & 15;
  const int hi8 = (lane >> 4) << 3;
  const uint32_t aAddrH = smaddr(AhB + (wm + lane15) * 40 + hi8);
  const uint32_t aAddrL = smaddr(AlB + (wm + lane15) * 40 + hi8);
  const int bn = (lane & 7) + hi8;
  const int bk = lane & 8;
  const uint32_t bAddrH = smaddr(BhB + (wn + bn) * 40 + bk);
  const uint32_t bAddrL = smaddr(BlB + (wn + bn) * 40 + bk);

  auto loadTile = [&](int k0, int buf) {
#pragma unroll
    for (int u = tid; u < 512; u += 256) {
      int row = u >> 2, seg = u & 3;
      size_t ga = (size_t)(mBase + row) * 512 + k0 + seg * 8;
      int so = buf * 5120 + row * 40 + seg * 8;
      CP16(smaddr(AhB + so), Ah + ga);
      CP16(smaddr(AlB + so), Al + ga);
    }
    {
      int row = tid >> 2, seg = tid & 3;
      size_t ga = (size_t)(nBase + row) * 512 + k0 + seg * 8;
      int so = buf * 2560 + row * 40 + seg * 8;
      CP16(smaddr(BhB + so), Wh + ga);
      CP16(smaddr(BlB + so), Wl + ga);
    }
    CP_COMMIT();
  };

  float acc[2][4][4];
#pragma unroll
  for (int mi = 0; mi < 2; ++mi)
#pragma unroll
    for (int j = 0; j < 4; ++j)
#pragma unroll
      for (int q = 0; q < 4; ++q) acc[mi][j][q] = 0.0f;

  loadTile(0, 0);
  for (int t = 0; t < 16; ++t) {
    if (t < 15) { loadTile((t + 1) * 32, (t + 1) & 1); CP_WAIT1(); }
    else CP_WAIT0();
    __syncthreads();
    const uint32_t aOff = (uint32_t)((t & 1) * 10240);
    const uint32_t bOff = (uint32_t)((t & 1) * 5120);
#pragma unroll
    for (int kk = 0; kk < 32; kk += 16) {
      uint32_t ah[2][4], al[2][4];
#pragma unroll
      for (int mi = 0; mi < 2; ++mi) {
        LDSM_X4(ah[mi][0], ah[mi][1], ah[mi][2], ah[mi][3], aAddrH + aOff + (mi * 640 + kk) * 2);
        LDSM_X4(al[mi][0], al[mi][1], al[mi][2], al[mi][3], aAddrL + aOff + (mi * 640 + kk) * 2);
      }
      uint32_t bh[4][2], bl[4][2];
#pragma unroll
      for (int p = 0; p < 2; ++p) {
        LDSM_X4(bh[2 * p][0], bh[2 * p][1], bh[2 * p + 1][0], bh[2 * p + 1][1],
                bAddrH + bOff + (p * 640 + kk) * 2);
        LDSM_X4(bl[2 * p][0], bl[2 * p][1], bl[2 * p + 1][0], bl[2 * p + 1][1],
                bAddrL + bOff + (p * 640 + kk) * 2);
      }
#pragma unroll
      for (int mi = 0; mi < 2; ++mi)
#pragma unroll
        for (int j = 0; j < 4; ++j) {
          MMA_BF16(acc[mi][j], ah[mi], bh[j]);
          MMA_BF16(acc[mi][j], ah[mi], bl[j]);
          MMA_BF16(acc[mi][j], al[mi], bh[j]);
        }
    }
    __syncthreads();
  }

#pragma unroll
  for (int mi = 0; mi < 2; ++mi) {
    int row = mBase + wm + mi * 16 + g;
#pragma unroll
    for (int j = 0; j < 4; ++j) {
      int col = nBase + wn + j * 8 + t4 * 2;
      uint32_t hi, lo;
      split2(acc[mi][j][0], acc[mi][j][1], hi, lo);
      *(uint32_t*)(Ch + (size_t)row * 512 + col) = hi;
      *(uint32_t*)(Cl + (size_t)row * 512 + col) = lo;
      split2(acc[mi][j][2], acc[mi][j][3], hi, lo);
      *(uint32_t*)(Ch + (size_t)(row + 8) * 512 + col) = hi;
      *(uint32_t*)(Cl + (size_t)(row + 8) * 512 + col) = lo;
    }
  }
}

// ====== bf16x3 logits (single-buffer K=64, per-direction launch) ======
#define LOGITS_SMEM 55296
__global__ __launch_bounds__(256) void gemm_logits_mma(
    float* __restrict__ sc, const unsigned char* __restrict__ mg, int dir) {
  extern __shared__ __align__(16) u16 dyn[];
  u16* AhB = dyn;
  u16* AlB = dyn + 9216;
  u16* BhB = dyn + 18432;
  u16* BlB = dyn + 23040;

  const int bid = blockIdx.x;
  int Lq, Lk, x, y, z;
  const u16 *Qh, *Ql, *Kh, *Kl;
  float* Sd;
  const unsigned char *mqB, *mkB;
  if (dir == 0) {
    Lq = 512; Lk = 256;
    x = bid & 3; y = (bid >> 2) & 3; z = bid >> 4;
    Qh = (const u16*)(sc + 33554432); Ql = (const u16*)(sc + 37748736);
    Kh = (const u16*)(sc + 62914560); Kl = (const u16*)(sc + 65011712);
    Sd = sc;
    mqB = mg; mkB = mg + 16384;
  } else {
    Lq = 256; Lk = 512;
    x = bid & 1; y = (bid >> 1) & 7; z = bid >> 4;
    Qh = (const u16*)(sc + 58720256); Ql = (const u16*)(sc + 60817408);
    Kh = (const u16*)(sc + 41943040); Kl = (const u16*)(sc + 46137344);
    Sd = sc + 85458944;
    mqB = mg + 16384; mkB = mg;
  }
  const int tid = threadIdx.x;
  const int w = tid >> 5, lane = tid & 31;
  const int g = lane >> 2, t4 = lane & 3;
  const int wm = (w >> 1) * 32, wn = (w & 1) * 32;
  const int mBase = x * 128;
  const int nBase = y * 64;
  const int b = z >> 3, h = z & 7;
  const u16* Ahg = Qh + (size_t)b * Lq * 512 + h * 64;
  const u16* Alg = Ql + (size_t)b * Lq * 512 + h * 64;
  const u16* Bhg = Kh + (size_t)b * Lk * 512 + h * 64;
  const u16* Blg = Kl + (size_t)b * Lk * 512 + h * 64;
  float* C = Sd + (size_t)z * Lq * Lk;
  const unsigned char* mqb = mqB + b * Lq;
  const unsigned char* mkb = mkB + b * Lk;

  const int lane15 = lane & 15;
  const int hi8 = (lane >> 4) << 3;
  const uint32_t aAddrH = smaddr(AhB + (wm + lane15) * 72 + hi8);
  const uint32_t aAddrL = smaddr(AlB + (wm + lane15) * 72 + hi8);
  const int bn = (lane & 7) + hi8;
  const int bk = lane & 8;
  const uint32_t bAddrH = smaddr(BhB + (wn + bn) * 72 + bk);
  const uint32_t bAddrL = smaddr(BlB + (wn + bn) * 72 + bk);

#pragma unroll
  for (int u = tid; u < 1024; u += 256) {
    int row = u >> 3, seg = u & 7;
    size_t ga = (size_t)(mBase + row) * 512 + seg * 8;
    int so = row * 72 + seg * 8;
    CP16(smaddr(AhB + so), Ahg + ga);
    CP16(smaddr(AlB + so), Alg + ga);
  }
#pragma unroll
  for (int u = tid; u < 512; u += 256) {
    int row = u >> 3, seg = u & 7;
    size_t ga = (size_t)(nBase + row) * 512 + seg * 8;
    int so = row * 72 + seg * 8;
    CP16(smaddr(BhB + so), Bhg + ga);
    CP16(smaddr(BlB + so), Blg + ga);
  }
  CP_COMMIT();

  float acc[2][4][4];
#pragma unroll
  for (int mi = 0; mi < 2; ++mi)
#pragma unroll
    for (int j = 0; j < 4; ++j)
#pragma unroll
      for (int q = 0; q < 4; ++q) acc[mi][j][q] = 0.0f;

  CP_WAIT0();
  __syncthreads();
#pragma unroll
  for (int kk = 0; kk < 64; kk += 16) {
    uint32_t ah[2][4], al[2][4];
#pragma unroll
    for (int mi = 0; mi < 2; ++mi) {
      LDSM_X4(ah[mi][0], ah[mi][1], ah[mi][2], ah[mi][3], aAddrH + (mi * 1152 + kk) * 2);
      LDSM_X4(al[mi][0], al[mi][1], al[mi][2], al[mi][3], aAddrL + (mi * 1152 + kk) * 2);
    }
    uint32_t bh[4][2], bl[4][2];
#pragma unroll
    for (int p = 0; p < 2; ++p) {
      LDSM_X4(bh[2 * p][0], bh[2 * p][1], bh[2 * p + 1][0], bh[2 * p + 1][1],
              bAddrH + (p * 1152 + kk) * 2);
      LDSM_X4(bl[2 * p][0], bl[2 * p][1], bl[2 * p + 1][0], bl[2 * p + 1][1],
              bAddrL + (p * 1152 + kk) * 2);
    }
#pragma unroll
    for (int mi = 0; mi < 2; ++mi)
#pragma unroll
      for (int j = 0; j < 4; ++j) {
        MMA_BF16(acc[mi][j], ah[mi], bh[j]);
        MMA_BF16(acc[mi][j], ah[mi], bl[j]);
        MMA_BF16(acc[mi][j], al[mi], bh[j]);
      }
  }

#pragma unroll
  for (int mi = 0; mi < 2; ++mi) {
    int row = mBase + wm + mi * 16 + g;
    float p0 = mqb[row] ? 0.0f : 1.0e6f;
    float p1 = mqb[row + 8] ? 0.0f : 1.0e6f;
#pragma unroll
    for (int j = 0; j < 4; ++j) {
      int col = nBase + wn + j * 8 + t4 * 2;
      float c0 = mkb[col] ? 0.0f : 1.0e6f;
      float c1 = mkb[col + 1] ? 0.0f : 1.0e6f;
      *(float2*)(C + (size_t)row * Lk + col) =
          make_float2(acc[mi][j][0] - fmaxf(p0, c0), acc[mi][j][1] - fmaxf(p0, c1));
      *(float2*)(C + (size_t)(row + 8) * Lk + col) =
          make_float2(acc[mi][j][2] - fmaxf(p1, c0), acc[mi][j][3] - fmaxf(p1, c1));
    }
  }
}

// ---------------- softmax (per-direction launch) ----------------
template <int LK>
__device__ __forceinline__ void softmax_impl(
    float* __restrict__ S, const unsigned char* __restrict__ mq,
    float* __restrict__ alphaOut, int Lq, int l, int b, float* sbuf) {
  const int tid = threadIdx.x, w = tid >> 5, lane = tid & 31;
  const size_t abase = ((size_t)b * Lq + l) * (size_t)(LK * 8);

  if (!mq[b * Lq + l]) {
    for (int idx = tid; idx < LK * 8; idx += 256) alphaOut[abase + idx] = 0.0f;
#pragma unroll
    for (int h = 0; h < 8; ++h) {
      float* srow = S + ((size_t)(b * 8 + h) * Lq + l) * LK;
      for (int k = tid; k < LK; k += 256) srow[k] = 0.0f;
    }
    return;
  }

  float* srow = S + ((size_t)(b * 8 + w) * Lq + l) * LK;
  const int nit = LK / 32;
  float v[LK / 32];
  float mx = -3.0e38f;
#pragma unroll
  for (int i = 0; i < nit; ++i) { v[i] = srow[lane + 32 * i]; mx = fmaxf(mx, v[i]); }
#pragma unroll
  for (int o = 16; o > 0; o >>= 1) mx = fmaxf(mx, __shfl_xor_sync(0xffffffffu, mx, o));
  float sum = 0.0f;
#pragma unroll
  for (int i = 0; i < nit; ++i) { float e = __expf(v[i] - mx); v[i] = e; sum += e; }
#pragma unroll
  for (int o = 16; o > 0; o >>= 1) sum += __shfl_xor_sync(0xffffffffu, sum, o);
  float inv = 1.0f / sum;
  u16* arow = (u16*)srow;
#pragma unroll
  for (int i = 0; i < nit; ++i) {
    float a = v[i] * inv;
    sbuf[w * 513 + lane + 32 * i] = a;
    u16 hb = bf16bits(a);
    arow[lane + 32 * i] = hb;
    arow[LK + lane + 32 * i] = bf16bits(a - bf16val(hb));
  }
  __syncthreads();
#pragma unroll 4
  for (int idx = tid; idx < LK * 8; idx += 256) {
    int k = idx >> 3, h = idx & 7;
    alphaOut[abase + idx] = sbuf[h * 513 + k];
  }
}

__global__ __launch_bounds__(256) void softmax_dir(
    float* __restrict__ sc, const unsigned char* __restrict__ mg,
    float* __restrict__ out, int dir) {
  __shared__ float sbuf[8 * 513];
  const int bid = blockIdx.x;
  if (dir == 0) {
    int l = bid & 511, b = bid >> 9;
    softmax_impl<256>(sc, mg, out + 12607488u, 512, l, b, sbuf);
  } else {
    int l = bid & 255, b = bid >> 8;
    softmax_impl<512>(sc + 85458944, mg + 16384, out + 46161920u, 256, l, b, sbuf);
  }
}

// ====== bf16x3 AV (cp.async double-buffered, per-direction launch) ======
#define AV_SMEM 59392
__global__ __launch_bounds__(256) void gemm_av_mma(
    float* __restrict__ sc, float* __restrict__ out, int dir) {
  extern __shared__ __align__(16) u16 dyn[];
  u16* AhB = dyn;
  u16* AlB = dyn + 10240;
  u16* BhB = dyn + 20480;
  u16* BlB = dyn + 25088;

  const int bid = blockIdx.x;
  int Lq, Lk, x, z;
  const float* Sd;
  const u16 *Vh, *Vl;
  float* OutD;
  if (dir == 0) {
    Lq = 512; Lk = 256;
    x = bid & 3; z = bid >> 2;
    Sd = sc;
    Vh = (const u16*)(sc + 67108864); Vl = (const u16*)(sc + 69206016);
    OutD = out;
  } else {
    Lq = 256; Lk = 512;
    x = bid & 1; z = bid >> 1;
    Sd = sc + 85458944;
    Vh = (const u16*)(sc + 50331648); Vl = (const u16*)(sc + 54525952);
    OutD = out + 8388608;
  }
  const int tid = threadIdx.x;
  const int w = tid >> 5, lane = tid & 31;
  const int g = lane >> 2, t4 = lane & 3;
  const int wm = (w >> 1) * 32, wn = (w & 1) * 32;
  const int mBase = x * 128;
  const int b = z >> 3, h = z & 7;
  const u16* Abase = (const u16*)(Sd + (size_t)z * Lq * Lk);
  const size_t vbase = (size_t)b * Lk * 512 + h * 64;
  float* C = OutD + (size_t)b * Lq * 512 + h * 64;

  const int lane15 = lane & 15;
  const int hi8 = (lane >> 4) << 3;
  const uint32_t aAddrH = smaddr(AhB + (wm + lane15) * 40 + hi8);
  const uint32_t aAddrL = smaddr(AlB + (wm + lane15) * 40 + hi8);
  const int bkOff = (lane & 7) + (lane & 8);
  const uint32_t bAddrH = smaddr(BhB + bkOff * 72 + wn + hi8);
  const uint32_t bAddrL = smaddr(BlB + bkOff * 72 + wn + hi8);

  auto loadTile = [&](int k0, int buf) {
#pragma unroll
    for (int u = tid; u < 512; u += 256) {
      int row = u >> 2, seg = u & 3;
      const u16* ar = Abase + (size_t)(mBase + row) * 2 * Lk + k0 + seg * 8;
      int so = buf * 5120 + row * 40 + seg * 8;
      CP16(smaddr(AhB + so), ar);
      CP16(smaddr(AlB + so), ar + Lk);
    }
    {
      int row = tid >> 3, seg = tid & 7;
      size_t ga = vbase + (size_t)(k0 + row) * 512 + seg * 8;
      int so = buf * 2304 + row * 72 + seg * 8;
      CP16(smaddr(BhB + so), Vh + ga);
      CP16(smaddr(BlB + so), Vl + ga);
    }
    CP_COMMIT();
  };

  float acc[2][4][4];
#pragma unroll
  for (int mi = 0; mi < 2; ++mi)
#pragma unroll
    for (int j = 0; j < 4; ++j)
#pragma unroll
      for (int q = 0; q < 4; ++q) acc[mi][j][q] = 0.0f;

  const int T = Lk / 32;
  loadTile(0, 0);
  for (int t = 0; t < T; ++t) {
    if (t < T - 1) { loadTile((t + 1) * 32, (t + 1) & 1); CP_WAIT1(); }
    else CP_WAIT0();
    __syncthreads();
    const uint32_t aOff = (uint32_t)((t & 1) * 10240);
    const uint32_t bOff = (uint32_t)((t & 1) * 4608);
#pragma unroll
    for (int kk = 0; kk < 32; kk += 16) {
      uint32_t ah[2][4], al[2][4];
#pragma unroll
      for (int mi = 0; mi < 2; ++mi) {
        LDSM_X4(ah[mi][0], ah[mi][1], ah[mi][2], ah[mi][3], aAddrH + aOff + (mi * 640 + kk) * 2);
        LDSM_X4(al[mi][0], al[mi][1], al[mi][2], al[mi][3], aAddrL + aOff + (mi * 640 + kk) * 2);
      }
      uint32_t bh[4][2], bl[4][2];
#pragma unroll
      for (int p = 0; p < 2; ++p) {
        LDSM_X4_T(bh[2 * p][0], bh[2 * p][1], bh[2 * p + 1][0], bh[2 * p + 1][1],
                  bAddrH + bOff + (kk * 72 + p * 16) * 2);
        LDSM_X4_T(bl[2 * p][0], bl[2 * p][1], bl[2 * p + 1][0], bl[2 * p + 1][1],
                  bAddrL + bOff + (kk * 72 + p * 16) * 2);
      }
#pragma unroll
      for (int mi = 0; mi < 2; ++mi)
#pragma unroll
        for (int j = 0; j < 4; ++j) {
          MMA_BF16(acc[mi][j], ah[mi], bh[j]);
          MMA_BF16(acc[mi][j], ah[mi], bl[j]);
          MMA_BF16(acc[mi][j], al[mi], bh[j]);
        }
    }
    __syncthreads();
  }

#pragma unroll
  for (int mi = 0; mi < 2; ++mi) {
    int row = mBase + wm + mi * 16 + g;
#pragma unroll
    for (int j = 0; j < 4; ++j) {
      int col = wn + j * 8 + t4 * 2;
      *(float2*)(C + (size_t)row * 512 + col) = make_float2(acc[mi][j][0], acc[mi][j][1]);
      *(float2*)(C + (size_t)(row + 8) * 512 + col) = make_float2(acc[mi][j][2], acc[mi][j][3]);
    }
  }
}

// ---------------- launch ----------------
extern "C" void kernel_launch(void* const* d_in, const int* in_sizes, int n_in,
                              void* d_out, int out_size) {
  const float* protein = (const float*)d_in[0];
  const float* drug    = (const float*)d_in[1];
  const void*  mpraw   = d_in[2];
  const void*  mdraw   = d_in[3];
  const float* W[6] = {(const float*)d_in[4], (const float*)d_in[5], (const float*)d_in[6],
                       (const float*)d_in[7], (const float*)d_in[8], (const float*)d_in[9]};
  float* out = (float*)d_out;

  float* sc = nullptr;
  cudaGetSymbolAddress((void**)&sc, g_scratch);
  unsigned char* mg = nullptr;
  cudaGetSymbolAddress((void**)&mg, g_masks);

  u16* QPh = (u16*)(sc + 33554432);
  u16* PGH = (u16*)(sc + 71303168); u16* PGL = (u16*)(sc + 75497472);
  u16* DRH = (u16*)(sc + 79691776); u16* DRL = (u16*)(sc + 81788928);
  u16* WHb = (u16*)(sc + 83886080); u16* WLb = (u16*)(sc + 84672512);

  const size_t OFF_MP = 12582912;
  const size_t OFF_MD = 12599296;

  static cudaStream_t sB = nullptr;
  static cudaEvent_t evFork = nullptr, evJoin = nullptr;
  if (!sB) {
    cudaFuncSetAttribute(gemm_proj_mma, cudaFuncAttributeMaxDynamicSharedMemorySize, PROJ_SMEM);
    cudaFuncSetAttribute(gemm_logits_mma, cudaFuncAttributeMaxDynamicSharedMemorySize, LOGITS_SMEM);
    cudaFuncSetAttribute(gemm_av_mma, cudaFuncAttributeMaxDynamicSharedMemorySize, AV_SMEM);
    cudaStreamCreateWithFlags(&sB, cudaStreamNonBlocking);
    cudaEventCreateWithFlags(&evFork, cudaEventDisableTiming);
    cudaEventCreateWithFlags(&evJoin, cudaEventDisableTiming);
  }

  prep_all<<<3552, 256>>>(protein, drug,
                          (const float4*)W[0], (const float4*)W[1], (const float4*)W[2],
                          (const float4*)W[3], (const float4*)W[4], (const float4*)W[5],
                          mpraw, mdraw,
                          (uint2*)PGH, (uint2*)PGL, (uint2*)DRH, (uint2*)DRL,
                          (uint2*)WHb, (uint2*)WLb,
                          out + OFF_MP, out + OFF_MD);

  gemm_proj_mma<<<4608, 256, PROJ_SMEM>>>(PGH, PGL, DRH, DRL, WHb, WLb, QPh);

  // fork: dir2 chain on side stream, dir1 chain on default stream
  cudaEventRecord(evFork, 0);
  cudaStreamWaitEvent(sB, evFork, 0);

  gemm_logits_mma<<<4096, 256, LOGITS_SMEM, sB>>>(sc, mg, 1);
  softmax_dir<<<8192, 256, 0, sB>>>(sc, mg, out, 1);
  gemm_av_mma<<<512, 256, AV_SMEM, sB>>>(sc, out, 1);
  cudaEventRecord(evJoin, sB);

  gemm_logits_mma<<<4096, 256, LOGITS_SMEM>>>(sc, mg, 0);
  softmax_dir<<<16384, 256>>>(sc, mg, out, 0);
  gemm_av_mma<<<1024, 256, AV_SMEM>>>(sc, out, 0);

  cudaStreamWaitEvent(0, evJoin, 0);

  (void)in_sizes; (void)n_in; (void)out_size;
}